// round 1
// baseline (speedup 1.0000x reference)
#include <cuda_runtime.h>
#include <math_constants.h>

// Problem constants
#define CB   16
#define CL   512
#define CDM  768
#define CS   2048
#define CDL  4096
#define CH   8
#define CE   96
#define CHE  768   // H*E

// Scratch (allocation-free: device globals)
__device__ float g_Q[(size_t)CB * CL * CHE];   // 8192 x 768
__device__ float g_K[(size_t)CS * CHE];        // 2048 x 768
__device__ float g_V[(size_t)CS * CHE];        // 2048 x 768
__device__ float g_rep[(size_t)CB * CL * CHE]; // 8192 x 768

// ============================================================================
// SGEMM: C[M,N] = A[M,K] @ B[K,N] + bias[N]   (all row-major, dims % {128,16}==0)
// 128x128 tile, BK=16, 256 threads, 8x8 micro-tile with split-4 column mapping
// (cols {tx*4..tx*4+3, 64+tx*4..}) for conflict-free LDS.128.
// ============================================================================
#define BM 128
#define BN 128
#define BK 16

__global__ __launch_bounds__(256, 2)
void sgemm_bias(const float* __restrict__ A, const float* __restrict__ Bm,
                const float* __restrict__ bias, float* __restrict__ C,
                int M, int N, int K)
{
    __shared__ float As[BK][BM + 4];
    __shared__ float Bs[BK][BN + 4];

    const int tid = threadIdx.x;
    const int tx = tid & 15;        // 0..15 (N micro index)
    const int ty = tid >> 4;        // 0..15 (M micro index)
    const int bn = blockIdx.x * BN;
    const int bm = blockIdx.y * BM;

    // A-tile load: 128 rows x 16 cols; thread loads 2 float4 (rows a_r, a_r+64)
    const int a_r = tid >> 2;          // 0..63
    const int a_c = (tid & 3) << 2;    // 0,4,8,12
    // B-tile load: 16 rows x 128 cols; thread loads 2 float4 (rows b_r, b_r+8)
    const int b_r = tid >> 5;          // 0..7
    const int b_c = (tid & 31) << 2;   // 0..124

    float acc[8][8];
#pragma unroll
    for (int i = 0; i < 8; ++i)
#pragma unroll
        for (int j = 0; j < 8; ++j) acc[i][j] = 0.0f;

    const float* Aptr = A + (size_t)bm * K;
    const float* Bptr = Bm + bn;

    for (int kk = 0; kk < K; kk += BK) {
#pragma unroll
        for (int rr = 0; rr < BM; rr += 64) {
            float4 v = *(const float4*)(Aptr + (size_t)(a_r + rr) * K + kk + a_c);
            As[a_c + 0][a_r + rr] = v.x;
            As[a_c + 1][a_r + rr] = v.y;
            As[a_c + 2][a_r + rr] = v.z;
            As[a_c + 3][a_r + rr] = v.w;
        }
#pragma unroll
        for (int rr = 0; rr < BK; rr += 8) {
            *(float4*)&Bs[b_r + rr][b_c] =
                *(const float4*)(Bptr + (size_t)(kk + b_r + rr) * N + b_c);
        }
        __syncthreads();

#pragma unroll
        for (int k = 0; k < BK; ++k) {
            float a[8], b[8];
            *(float4*)&a[0] = *(float4*)&As[k][ty * 4];
            *(float4*)&a[4] = *(float4*)&As[k][64 + ty * 4];
            *(float4*)&b[0] = *(float4*)&Bs[k][tx * 4];
            *(float4*)&b[4] = *(float4*)&Bs[k][64 + tx * 4];
#pragma unroll
            for (int i = 0; i < 8; ++i)
#pragma unroll
                for (int j = 0; j < 8; ++j)
                    acc[i][j] += a[i] * b[j];
        }
        __syncthreads();
    }

    // Epilogue: rows {bm+ty*4+i, bm+64+ty*4+i}, cols {bn+tx*4+j, bn+64+tx*4+j}
#pragma unroll
    for (int ih = 0; ih < 2; ++ih) {
#pragma unroll
        for (int i = 0; i < 4; ++i) {
            const int row = bm + ih * 64 + ty * 4 + i;
#pragma unroll
            for (int jh = 0; jh < 2; ++jh) {
                const int col = bn + jh * 64 + tx * 4;
                float4 o;
                o.x = acc[ih * 4 + i][jh * 4 + 0] + bias[col + 0];
                o.y = acc[ih * 4 + i][jh * 4 + 1] + bias[col + 1];
                o.z = acc[ih * 4 + i][jh * 4 + 2] + bias[col + 2];
                o.w = acc[ih * 4 + i][jh * 4 + 3] + bias[col + 3];
                *(float4*)&C[(size_t)row * N + col] = o;
            }
        }
    }
}

// ============================================================================
// Flash attention: per block = one (b,h) and a 64-query tile.
// Online softmax over S=2048 in chunks of 64. E=96.
// 256 threads: ty=tid/16 owns query rows ty*4+i; tx=tid%16.
// Score cols per thread: tx+16*j (conflict-free K-row LDS.128).
// O cols per thread: tx*6+j.
// ============================================================================
#define AT_M 64
#define AT_N 64
#define KV_STRIDE 100   // 96 + 4 pad
#define PS_STRIDE 68    // 64 + 4 pad

__global__ __launch_bounds__(256, 2)
void attn_kernel()
{
    extern __shared__ float sm[];
    float* Qs = sm;                          // 64 * 100
    float* Ks = Qs + AT_M * KV_STRIDE;       // 64 * 100
    float* Vs = Ks + AT_N * KV_STRIDE;       // 64 * 100
    float* Ps = Vs + AT_N * KV_STRIDE;       // 64 * 68

    const int tid = threadIdx.x;
    const int tx = tid & 15;
    const int ty = tid >> 4;
    const int bh = blockIdx.y;
    const int b = bh >> 3;      // /H
    const int h = bh & 7;       // %H
    const int q0 = blockIdx.x * AT_M;

    const float qscale = 0.1020620726159658f;  // 1/sqrt(96)

    // Load + scale Q tile: 64 x 96 = 1536 float4
    for (int i = tid; i < AT_M * (CE / 4); i += 256) {
        const int r = i / (CE / 4);
        const int c4 = (i % (CE / 4)) * 4;
        float4 v = *(const float4*)&g_Q[((size_t)(b * CL + q0 + r)) * CHE + h * CE + c4];
        Qs[r * KV_STRIDE + c4 + 0] = v.x * qscale;
        Qs[r * KV_STRIDE + c4 + 1] = v.y * qscale;
        Qs[r * KV_STRIDE + c4 + 2] = v.z * qscale;
        Qs[r * KV_STRIDE + c4 + 3] = v.w * qscale;
    }

    float acc[4][6];
#pragma unroll
    for (int i = 0; i < 4; ++i)
#pragma unroll
        for (int j = 0; j < 6; ++j) acc[i][j] = 0.0f;
    float m_i[4], l_i[4];
#pragma unroll
    for (int i = 0; i < 4; ++i) { m_i[i] = -1e30f; l_i[i] = 0.0f; }

    __syncthreads();

    for (int s0 = 0; s0 < CS; s0 += AT_N) {
        // Load K,V chunk (64 x 96 each)
        for (int i = tid; i < AT_N * (CE / 4); i += 256) {
            const int r = i / (CE / 4);
            const int c4 = (i % (CE / 4)) * 4;
            const size_t off = ((size_t)(s0 + r)) * CHE + h * CE + c4;
            float4 kv = *(const float4*)&g_K[off];
            Ks[r * KV_STRIDE + c4 + 0] = kv.x;
            Ks[r * KV_STRIDE + c4 + 1] = kv.y;
            Ks[r * KV_STRIDE + c4 + 2] = kv.z;
            Ks[r * KV_STRIDE + c4 + 3] = kv.w;
            float4 vv = *(const float4*)&g_V[off];
            Vs[r * KV_STRIDE + c4 + 0] = vv.x;
            Vs[r * KV_STRIDE + c4 + 1] = vv.y;
            Vs[r * KV_STRIDE + c4 + 2] = vv.z;
            Vs[r * KV_STRIDE + c4 + 3] = vv.w;
        }
        __syncthreads();

        // Scores: S[ty*4+i][tx+16*j] = Qrow . Krow
        float sc[4][4];
#pragma unroll
        for (int i = 0; i < 4; ++i)
#pragma unroll
            for (int j = 0; j < 4; ++j) sc[i][j] = 0.0f;

#pragma unroll
        for (int k = 0; k < CE; k += 4) {
            float4 q[4], kr[4];
#pragma unroll
            for (int i = 0; i < 4; ++i)
                q[i] = *(float4*)&Qs[(ty * 4 + i) * KV_STRIDE + k];
#pragma unroll
            for (int j = 0; j < 4; ++j)
                kr[j] = *(float4*)&Ks[(tx + 16 * j) * KV_STRIDE + k];
#pragma unroll
            for (int i = 0; i < 4; ++i) {
#pragma unroll
                for (int j = 0; j < 4; ++j) {
                    sc[i][j] += q[i].x * kr[j].x + q[i].y * kr[j].y
                              + q[i].z * kr[j].z + q[i].w * kr[j].w;
                }
            }
        }

        // Online softmax per row (reduce across 16 tx lanes, width-16 butterflies)
        float oscale[4];
#pragma unroll
        for (int i = 0; i < 4; ++i) {
            float cm = fmaxf(fmaxf(sc[i][0], sc[i][1]), fmaxf(sc[i][2], sc[i][3]));
#pragma unroll
            for (int d = 8; d >= 1; d >>= 1)
                cm = fmaxf(cm, __shfl_xor_sync(0xffffffffu, cm, d, 16));
            const float newm = fmaxf(m_i[i], cm);
            const float sfac = __expf(m_i[i] - newm);
            float rs = 0.0f;
            const int r = ty * 4 + i;
#pragma unroll
            for (int j = 0; j < 4; ++j) {
                const float p = __expf(sc[i][j] - newm);
                Ps[r * PS_STRIDE + tx + 16 * j] = p;
                rs += p;
            }
#pragma unroll
            for (int d = 8; d >= 1; d >>= 1)
                rs += __shfl_xor_sync(0xffffffffu, rs, d, 16);
            m_i[i] = newm;
            l_i[i] = l_i[i] * sfac + rs;
            oscale[i] = sfac;
        }
#pragma unroll
        for (int i = 0; i < 4; ++i)
#pragma unroll
            for (int j = 0; j < 6; ++j) acc[i][j] *= oscale[i];

        __syncwarp();

        // PV: O[ty*4+i][tx*6+j] += sum_k P[r][k] * V[k][c]
#pragma unroll 4
        for (int k = 0; k < AT_N; k += 4) {
            float4 p[4];
#pragma unroll
            for (int i = 0; i < 4; ++i)
                p[i] = *(float4*)&Ps[(ty * 4 + i) * PS_STRIDE + k];
#pragma unroll
            for (int kk = 0; kk < 4; ++kk) {
                float v[6];
                const float* vrow = &Vs[(k + kk) * KV_STRIDE + tx * 6];
                float2 v01 = *(const float2*)&vrow[0];
                float2 v23 = *(const float2*)&vrow[2];
                float2 v45 = *(const float2*)&vrow[4];
                v[0] = v01.x; v[1] = v01.y; v[2] = v23.x;
                v[3] = v23.y; v[4] = v45.x; v[5] = v45.y;
                const float pk[4] = {
                    kk == 0 ? p[0].x : kk == 1 ? p[0].y : kk == 2 ? p[0].z : p[0].w,
                    kk == 0 ? p[1].x : kk == 1 ? p[1].y : kk == 2 ? p[1].z : p[1].w,
                    kk == 0 ? p[2].x : kk == 1 ? p[2].y : kk == 2 ? p[2].z : p[2].w,
                    kk == 0 ? p[3].x : kk == 1 ? p[3].y : kk == 2 ? p[3].z : p[3].w };
#pragma unroll
                for (int i = 0; i < 4; ++i)
#pragma unroll
                    for (int j = 0; j < 6; ++j)
                        acc[i][j] += pk[i] * v[j];
            }
        }
        __syncthreads();
    }

    // Epilogue: normalize and write rep
#pragma unroll
    for (int i = 0; i < 4; ++i) {
        const float inv = 1.0f / l_i[i];
        const size_t base = ((size_t)(b * CL + q0 + ty * 4 + i)) * CHE + h * CE + tx * 6;
#pragma unroll
        for (int j = 0; j < 6; ++j)
            g_rep[base + j] = acc[i][j] * inv;
    }
}

// ============================================================================
// Launch
// ============================================================================
extern "C" void kernel_launch(void* const* d_in, const int* in_sizes, int n_in,
                              void* d_out, int out_size)
{
    const float* target = (const float*)d_in[0];
    const float* source = (const float*)d_in[1];
    const float* Wq = (const float*)d_in[2];
    const float* bq = (const float*)d_in[3];
    const float* Wk = (const float*)d_in[4];
    const float* bk = (const float*)d_in[5];
    const float* Wv = (const float*)d_in[6];
    const float* bv = (const float*)d_in[7];
    const float* Wo = (const float*)d_in[8];
    const float* bo = (const float*)d_in[9];
    float* out = (float*)d_out;

    float *Qp, *Kp, *Vp, *Rp;
    cudaGetSymbolAddress((void**)&Qp, g_Q);
    cudaGetSymbolAddress((void**)&Kp, g_K);
    cudaGetSymbolAddress((void**)&Vp, g_V);
    cudaGetSymbolAddress((void**)&Rp, g_rep);

    const dim3 blk(256);

    // Q = target @ Wq + bq   (8192 x 768, K=768)
    sgemm_bias<<<dim3(CHE / BN, (CB * CL) / BM), blk>>>(target, Wq, bq, Qp,
                                                        CB * CL, CHE, CDM);
    // K = source @ Wk + bk   (2048 x 768, K=4096)
    sgemm_bias<<<dim3(CHE / BN, CS / BM), blk>>>(source, Wk, bk, Kp, CS, CHE, CDL);
    // V = source @ Wv + bv
    sgemm_bias<<<dim3(CHE / BN, CS / BM), blk>>>(source, Wv, bv, Vp, CS, CHE, CDL);

    // Attention -> rep
    const size_t smem = (size_t)(3 * AT_M * KV_STRIDE + AT_M * PS_STRIDE) * sizeof(float);
    cudaFuncSetAttribute(attn_kernel, cudaFuncAttributeMaxDynamicSharedMemorySize,
                         (int)smem);
    attn_kernel<<<dim3(CL / AT_M, CB * CH), blk, smem>>>();

    // out = rep @ Wo + bo    (8192 x 4096, K=768)
    sgemm_bias<<<dim3(CDL / BN, (CB * CL) / BM), blk>>>(Rp, Wo, bo, out,
                                                        CB * CL, CDL, CHE);
}

// round 2
// speedup vs baseline: 1.7764x; 1.7764x over previous
#include <cuda_runtime.h>
#include <math_constants.h>
#include <stdint.h>

// Problem constants
#define CB   16
#define CL   512
#define CDM  768
#define CS   2048
#define CDL  4096
#define CH   8
#define CE   96
#define CHE  768   // H*E

// Scratch (allocation-free: device globals)
__device__ float g_Q[(size_t)CB * CL * CHE];   // 8192 x 768
__device__ float g_K[(size_t)CS * CHE];        // 2048 x 768
__device__ float g_V[(size_t)CS * CHE];        // 2048 x 768
__device__ float g_rep[(size_t)CB * CL * CHE]; // 8192 x 768

// ============================================================================
// TF32 tensor-core GEMM: C[M,N] = A[M,K] @ B[K,N] + bias[N]  (row-major)
// 128x128x32 tile, 256 threads = 8 warps (2 M x 4 N), warp tile 64x32,
// mma.sync.m16n8k8.tf32, cp.async double-buffered smem.
// If gridDim.z==2, blockIdx.z selects (B0,bias0,C0) vs (B1,bias1,C1) (fused K/V).
// ============================================================================
#define GBM 128
#define GBN 128
#define GBK 32
#define AS_STRIDE 36    // banks (4m+k) conflict-free for frag loads
#define BS_STRIDE 136   // banks (8k+n) conflict-free for frag loads

__device__ __forceinline__ uint32_t f2tf32(float x) {
    uint32_t r;
    asm("cvt.rna.tf32.f32 %0, %1;" : "=r"(r) : "f"(x));
    return r;
}

__device__ __forceinline__ void mma_tf32(float* d, const uint32_t* a, const uint32_t* b) {
    asm volatile(
        "mma.sync.aligned.m16n8k8.row.col.f32.tf32.tf32.f32 "
        "{%0,%1,%2,%3}, {%4,%5,%6,%7}, {%8,%9}, {%0,%1,%2,%3};"
        : "+f"(d[0]), "+f"(d[1]), "+f"(d[2]), "+f"(d[3])
        : "r"(a[0]), "r"(a[1]), "r"(a[2]), "r"(a[3]), "r"(b[0]), "r"(b[1]));
}

__device__ __forceinline__ void cp_async16(uint32_t dst, const void* src) {
    asm volatile("cp.async.cg.shared.global [%0], [%1], 16;\n" :: "r"(dst), "l"(src));
}

__global__ __launch_bounds__(256, 2)
void gemm_tf32(const float* __restrict__ A,
               const float* __restrict__ B0, const float* __restrict__ bias0,
               float* __restrict__ C0,
               const float* __restrict__ B1, const float* __restrict__ bias1,
               float* __restrict__ C1,
               int M, int N, int K)
{
    extern __shared__ float smem[];
    const float* Bg   = (blockIdx.z == 0) ? B0 : B1;
    const float* bias = (blockIdx.z == 0) ? bias0 : bias1;
    float*       C    = (blockIdx.z == 0) ? C0 : C1;

    float* As = smem;                             // 2 x 128 x 36
    float* Bs = smem + 2 * GBM * AS_STRIDE;       // 2 x 32 x 136

    const int tid  = threadIdx.x;
    const int wid  = tid >> 5;
    const int lane = tid & 31;
    const int rb = (wid & 1) * 64;   // warp M offset
    const int nb = (wid >> 1) * 32;  // warp N offset
    const int g = lane >> 2;         // group id (0..7)
    const int c = lane & 3;          // thread in group (0..3)

    const int bm = blockIdx.y * GBM;
    const int bn = blockIdx.x * GBN;

    // cp.async thread assignments
    const int am  = tid >> 3;            // 0..31  (A row)
    const int ak  = (tid & 7) << 2;      // 0..28  (A col, float4)
    const int bk  = tid >> 5;            // 0..7   (B row)
    const int bn4 = (tid & 31) << 2;     // 0..124 (B col, float4)

    float acc[4][4][4];
#pragma unroll
    for (int mt = 0; mt < 4; ++mt)
#pragma unroll
        for (int nt = 0; nt < 4; ++nt)
#pragma unroll
            for (int r = 0; r < 4; ++r) acc[mt][nt][r] = 0.0f;

    const uint32_t sAs = (uint32_t)__cvta_generic_to_shared(As);
    const uint32_t sBs = (uint32_t)__cvta_generic_to_shared(Bs);

    auto load_tiles = [&](int buf, int kk) {
        const uint32_t a_base = sAs + buf * (GBM * AS_STRIDE * 4);
        const uint32_t b_base = sBs + buf * (GBK * BS_STRIDE * 4);
#pragma unroll
        for (int mm = 0; mm < GBM; mm += 32)
            cp_async16(a_base + ((am + mm) * AS_STRIDE + ak) * 4,
                       A + (size_t)(bm + am + mm) * K + kk + ak);
#pragma unroll
        for (int k2 = 0; k2 < GBK; k2 += 8)
            cp_async16(b_base + ((bk + k2) * BS_STRIDE + bn4) * 4,
                       Bg + (size_t)(kk + bk + k2) * N + bn + bn4);
        asm volatile("cp.async.commit_group;\n" ::);
    };

    const int NIT = K / GBK;
    load_tiles(0, 0);
    int buf = 0;

    for (int it = 0; it < NIT; ++it) {
        if (it + 1 < NIT) {
            load_tiles(buf ^ 1, (it + 1) * GBK);
            asm volatile("cp.async.wait_group 1;\n" ::);
        } else {
            asm volatile("cp.async.wait_group 0;\n" ::);
        }
        __syncthreads();

        const float* Ab = As + buf * GBM * AS_STRIDE;
        const float* Bb = Bs + buf * GBK * BS_STRIDE;

#pragma unroll
        for (int ks = 0; ks < 4; ++ks) {
            const int k0 = ks * 8;
            uint32_t af[4][4], bf[4][2];
#pragma unroll
            for (int mt = 0; mt < 4; ++mt) {
                const float* p0 = Ab + (rb + mt * 16 + g) * AS_STRIDE + k0 + c;
                const float* p1 = p0 + 8 * AS_STRIDE;
                af[mt][0] = f2tf32(p0[0]);
                af[mt][1] = f2tf32(p1[0]);
                af[mt][2] = f2tf32(p0[4]);
                af[mt][3] = f2tf32(p1[4]);
            }
#pragma unroll
            for (int nt = 0; nt < 4; ++nt) {
                const float* p = Bb + (k0 + c) * BS_STRIDE + nb + nt * 8 + g;
                bf[nt][0] = f2tf32(p[0]);
                bf[nt][1] = f2tf32(p[4 * BS_STRIDE]);
            }
#pragma unroll
            for (int mt = 0; mt < 4; ++mt)
#pragma unroll
                for (int nt = 0; nt < 4; ++nt)
                    mma_tf32(acc[mt][nt], af[mt], bf[nt]);
        }
        __syncthreads();
        buf ^= 1;
    }

    // Epilogue: c0,c1 at (row, 2c), c2,c3 at (row+8, 2c)
#pragma unroll
    for (int mt = 0; mt < 4; ++mt) {
        const int row0 = bm + rb + mt * 16 + g;
#pragma unroll
        for (int nt = 0; nt < 4; ++nt) {
            const int col = bn + nb + nt * 8 + 2 * c;
            const float2 bv = *(const float2*)&bias[col];
            float2 o0 = { acc[mt][nt][0] + bv.x, acc[mt][nt][1] + bv.y };
            *(float2*)&C[(size_t)row0 * N + col] = o0;
            float2 o1 = { acc[mt][nt][2] + bv.x, acc[mt][nt][3] + bv.y };
            *(float2*)&C[(size_t)(row0 + 8) * N + col] = o1;
        }
    }
}

#define GEMM_SMEM ((2 * GBM * AS_STRIDE + 2 * GBK * BS_STRIDE) * 4)

// ============================================================================
// Flash attention (unchanged from R0): per block = one (b,h), 64-query tile.
// ============================================================================
#define AT_M 64
#define AT_N 64
#define KV_STRIDE 100   // 96 + 4 pad
#define PS_STRIDE 68    // 64 + 4 pad

__global__ __launch_bounds__(256, 2)
void attn_kernel()
{
    extern __shared__ float sm[];
    float* Qs = sm;                          // 64 * 100
    float* Ks = Qs + AT_M * KV_STRIDE;       // 64 * 100
    float* Vs = Ks + AT_N * KV_STRIDE;       // 64 * 100
    float* Ps = Vs + AT_N * KV_STRIDE;       // 64 * 68

    const int tid = threadIdx.x;
    const int tx = tid & 15;
    const int ty = tid >> 4;
    const int bh = blockIdx.y;
    const int b = bh >> 3;      // /H
    const int h = bh & 7;       // %H
    const int q0 = blockIdx.x * AT_M;

    const float qscale = 0.1020620726159658f;  // 1/sqrt(96)

    for (int i = tid; i < AT_M * (CE / 4); i += 256) {
        const int r = i / (CE / 4);
        const int c4 = (i % (CE / 4)) * 4;
        float4 v = *(const float4*)&g_Q[((size_t)(b * CL + q0 + r)) * CHE + h * CE + c4];
        Qs[r * KV_STRIDE + c4 + 0] = v.x * qscale;
        Qs[r * KV_STRIDE + c4 + 1] = v.y * qscale;
        Qs[r * KV_STRIDE + c4 + 2] = v.z * qscale;
        Qs[r * KV_STRIDE + c4 + 3] = v.w * qscale;
    }

    float acc[4][6];
#pragma unroll
    for (int i = 0; i < 4; ++i)
#pragma unroll
        for (int j = 0; j < 6; ++j) acc[i][j] = 0.0f;
    float m_i[4], l_i[4];
#pragma unroll
    for (int i = 0; i < 4; ++i) { m_i[i] = -1e30f; l_i[i] = 0.0f; }

    __syncthreads();

    for (int s0 = 0; s0 < CS; s0 += AT_N) {
        for (int i = tid; i < AT_N * (CE / 4); i += 256) {
            const int r = i / (CE / 4);
            const int c4 = (i % (CE / 4)) * 4;
            const size_t off = ((size_t)(s0 + r)) * CHE + h * CE + c4;
            float4 kv = *(const float4*)&g_K[off];
            Ks[r * KV_STRIDE + c4 + 0] = kv.x;
            Ks[r * KV_STRIDE + c4 + 1] = kv.y;
            Ks[r * KV_STRIDE + c4 + 2] = kv.z;
            Ks[r * KV_STRIDE + c4 + 3] = kv.w;
            float4 vv = *(const float4*)&g_V[off];
            Vs[r * KV_STRIDE + c4 + 0] = vv.x;
            Vs[r * KV_STRIDE + c4 + 1] = vv.y;
            Vs[r * KV_STRIDE + c4 + 2] = vv.z;
            Vs[r * KV_STRIDE + c4 + 3] = vv.w;
        }
        __syncthreads();

        float sc[4][4];
#pragma unroll
        for (int i = 0; i < 4; ++i)
#pragma unroll
            for (int j = 0; j < 4; ++j) sc[i][j] = 0.0f;

#pragma unroll
        for (int k = 0; k < CE; k += 4) {
            float4 q[4], kr[4];
#pragma unroll
            for (int i = 0; i < 4; ++i)
                q[i] = *(float4*)&Qs[(ty * 4 + i) * KV_STRIDE + k];
#pragma unroll
            for (int j = 0; j < 4; ++j)
                kr[j] = *(float4*)&Ks[(tx + 16 * j) * KV_STRIDE + k];
#pragma unroll
            for (int i = 0; i < 4; ++i) {
#pragma unroll
                for (int j = 0; j < 4; ++j) {
                    sc[i][j] += q[i].x * kr[j].x + q[i].y * kr[j].y
                              + q[i].z * kr[j].z + q[i].w * kr[j].w;
                }
            }
        }

        float oscale[4];
#pragma unroll
        for (int i = 0; i < 4; ++i) {
            float cm = fmaxf(fmaxf(sc[i][0], sc[i][1]), fmaxf(sc[i][2], sc[i][3]));
#pragma unroll
            for (int d = 8; d >= 1; d >>= 1)
                cm = fmaxf(cm, __shfl_xor_sync(0xffffffffu, cm, d, 16));
            const float newm = fmaxf(m_i[i], cm);
            const float sfac = __expf(m_i[i] - newm);
            float rs = 0.0f;
            const int r = ty * 4 + i;
#pragma unroll
            for (int j = 0; j < 4; ++j) {
                const float p = __expf(sc[i][j] - newm);
                Ps[r * PS_STRIDE + tx + 16 * j] = p;
                rs += p;
            }
#pragma unroll
            for (int d = 8; d >= 1; d >>= 1)
                rs += __shfl_xor_sync(0xffffffffu, rs, d, 16);
            m_i[i] = newm;
            l_i[i] = l_i[i] * sfac + rs;
            oscale[i] = sfac;
        }
#pragma unroll
        for (int i = 0; i < 4; ++i)
#pragma unroll
            for (int j = 0; j < 6; ++j) acc[i][j] *= oscale[i];

        __syncwarp();

#pragma unroll 4
        for (int k = 0; k < AT_N; k += 4) {
            float4 p[4];
#pragma unroll
            for (int i = 0; i < 4; ++i)
                p[i] = *(float4*)&Ps[(ty * 4 + i) * PS_STRIDE + k];
#pragma unroll
            for (int kk = 0; kk < 4; ++kk) {
                float v[6];
                const float* vrow = &Vs[(k + kk) * KV_STRIDE + tx * 6];
                float2 v01 = *(const float2*)&vrow[0];
                float2 v23 = *(const float2*)&vrow[2];
                float2 v45 = *(const float2*)&vrow[4];
                v[0] = v01.x; v[1] = v01.y; v[2] = v23.x;
                v[3] = v23.y; v[4] = v45.x; v[5] = v45.y;
                const float pk[4] = {
                    kk == 0 ? p[0].x : kk == 1 ? p[0].y : kk == 2 ? p[0].z : p[0].w,
                    kk == 0 ? p[1].x : kk == 1 ? p[1].y : kk == 2 ? p[1].z : p[1].w,
                    kk == 0 ? p[2].x : kk == 1 ? p[2].y : kk == 2 ? p[2].z : p[2].w,
                    kk == 0 ? p[3].x : kk == 1 ? p[3].y : kk == 2 ? p[3].z : p[3].w };
#pragma unroll
                for (int i = 0; i < 4; ++i)
#pragma unroll
                    for (int j = 0; j < 6; ++j)
                        acc[i][j] += pk[i] * v[j];
            }
        }
        __syncthreads();
    }

#pragma unroll
    for (int i = 0; i < 4; ++i) {
        const float inv = 1.0f / l_i[i];
        const size_t base = ((size_t)(b * CL + q0 + ty * 4 + i)) * CHE + h * CE + tx * 6;
#pragma unroll
        for (int j = 0; j < 6; ++j)
            g_rep[base + j] = acc[i][j] * inv;
    }
}

// ============================================================================
// Launch
// ============================================================================
extern "C" void kernel_launch(void* const* d_in, const int* in_sizes, int n_in,
                              void* d_out, int out_size)
{
    const float* target = (const float*)d_in[0];
    const float* source = (const float*)d_in[1];
    const float* Wq = (const float*)d_in[2];
    const float* bq = (const float*)d_in[3];
    const float* Wk = (const float*)d_in[4];
    const float* bk = (const float*)d_in[5];
    const float* Wv = (const float*)d_in[6];
    const float* bv = (const float*)d_in[7];
    const float* Wo = (const float*)d_in[8];
    const float* bo = (const float*)d_in[9];
    float* out = (float*)d_out;

    float *Qp, *Kp, *Vp, *Rp;
    cudaGetSymbolAddress((void**)&Qp, g_Q);
    cudaGetSymbolAddress((void**)&Kp, g_K);
    cudaGetSymbolAddress((void**)&Vp, g_V);
    cudaGetSymbolAddress((void**)&Rp, g_rep);

    cudaFuncSetAttribute(gemm_tf32, cudaFuncAttributeMaxDynamicSharedMemorySize,
                         GEMM_SMEM);

    const dim3 blk(256);

    // Q = target @ Wq + bq   (8192 x 768, K=768)
    gemm_tf32<<<dim3(CHE / GBN, (CB * CL) / GBM, 1), blk, GEMM_SMEM>>>(
        target, Wq, bq, Qp, Wq, bq, Qp, CB * CL, CHE, CDM);

    // K and V projections fused via blockIdx.z  (2048 x 768, K=4096)
    gemm_tf32<<<dim3(CHE / GBN, CS / GBM, 2), blk, GEMM_SMEM>>>(
        source, Wk, bk, Kp, Wv, bv, Vp, CS, CHE, CDL);

    // Attention -> rep
    const size_t smem = (size_t)(3 * AT_M * KV_STRIDE + AT_M * PS_STRIDE) * sizeof(float);
    cudaFuncSetAttribute(attn_kernel, cudaFuncAttributeMaxDynamicSharedMemorySize,
                         (int)smem);
    attn_kernel<<<dim3(CL / AT_M, CB * CH), blk, smem>>>();

    // out = rep @ Wo + bo    (8192 x 4096, K=768)
    gemm_tf32<<<dim3(CDL / GBN, (CB * CL) / GBM, 1), blk, GEMM_SMEM>>>(
        Rp, Wo, bo, out, Wo, bo, out, CB * CL, CDL, CHE);
}

// round 4
// speedup vs baseline: 5.1530x; 2.9008x over previous
#include <cuda_runtime.h>
#include <math_constants.h>
#include <stdint.h>

// Problem constants
#define CB   16
#define CL   512
#define CDM  768
#define CS   2048
#define CDL  4096
#define CH   8
#define CE   96
#define CHE  768   // H*E

// Scratch (allocation-free: device globals)
__device__ float g_Q[(size_t)CB * CL * CHE];   // 8192 x 768 (tf32-rounded)
__device__ float g_K[(size_t)CS * CHE];        // 2048 x 768 (tf32-rounded)
__device__ float g_V[(size_t)CS * CHE];        // 2048 x 768 (tf32-rounded)
__device__ float g_rep[(size_t)CB * CL * CHE]; // 8192 x 768 (tf32-rounded)
// Pre-rounded copies of GEMM inputs (low 13 mantissa bits zeroed, rna)
__device__ float g_tgt[(size_t)CB * CL * CDM];
__device__ float g_src[(size_t)CS * CDL];
__device__ float g_wq[(size_t)CDM * CHE];
__device__ float g_wk[(size_t)CDL * CHE];
__device__ float g_wv[(size_t)CDL * CHE];
__device__ float g_wo[(size_t)CHE * CDL];

__device__ __forceinline__ float rna_tf32(float x) {
    uint32_t r;
    asm("cvt.rna.tf32.f32 %0, %1;" : "=r"(r) : "f"(x));
    return __uint_as_float(r);
}

__device__ __forceinline__ float ex2(float x) {
    float y;
    asm("ex2.approx.f32 %0, %1;" : "=f"(y) : "f"(x));
    return y;
}

__device__ __forceinline__ void mma_tf32(float* d, const uint32_t* a, const uint32_t* b) {
    asm volatile(
        "mma.sync.aligned.m16n8k8.row.col.f32.tf32.tf32.f32 "
        "{%0,%1,%2,%3}, {%4,%5,%6,%7}, {%8,%9}, {%0,%1,%2,%3};"
        : "+f"(d[0]), "+f"(d[1]), "+f"(d[2]), "+f"(d[3])
        : "r"(a[0]), "r"(a[1]), "r"(a[2]), "r"(a[3]), "r"(b[0]), "r"(b[1]));
}

__device__ __forceinline__ void cp_async16(uint32_t dst, const void* src) {
    asm volatile("cp.async.cg.shared.global [%0], [%1], 16;\n" :: "r"(dst), "l"(src));
}

// ============================================================================
// Elementwise tf32 pre-round (rna)
// ============================================================================
__global__ void round_tf32_kernel(const float4* __restrict__ src,
                                  float4* __restrict__ dst, int n4)
{
    int i = blockIdx.x * blockDim.x + threadIdx.x;
    if (i < n4) {
        float4 v = src[i];
        v.x = rna_tf32(v.x); v.y = rna_tf32(v.y);
        v.z = rna_tf32(v.z); v.w = rna_tf32(v.w);
        dst[i] = v;
    }
}

// ============================================================================
// TF32 tensor-core GEMM (inputs pre-rounded; no cvt in mainloop).
// C[M,N] = A[M,K] @ B[K,N] + bias[N]; optionally rna-round outputs.
// 128x128x32 tile, 256 threads = 8 warps (2Mx4N), warp tile 64x32.
// If gridDim.z==2, blockIdx.z selects (B0,bias0,C0) vs (B1,bias1,C1).
// ============================================================================
#define GBM 128
#define GBN 128
#define GBK 32
#define AS_STRIDE 36
#define BS_STRIDE 136

__global__ __launch_bounds__(256, 2)
void gemm_tf32(const float* __restrict__ A,
               const float* __restrict__ B0, const float* __restrict__ bias0,
               float* __restrict__ C0,
               const float* __restrict__ B1, const float* __restrict__ bias1,
               float* __restrict__ C1,
               int M, int N, int K, int round_out)
{
    extern __shared__ float smem[];
    const float* Bg   = (blockIdx.z == 0) ? B0 : B1;
    const float* bias = (blockIdx.z == 0) ? bias0 : bias1;
    float*       C    = (blockIdx.z == 0) ? C0 : C1;

    float* As = smem;
    float* Bs = smem + 2 * GBM * AS_STRIDE;

    const int tid  = threadIdx.x;
    const int wid  = tid >> 5;
    const int lane = tid & 31;
    const int rb = (wid & 1) * 64;
    const int nb = (wid >> 1) * 32;
    const int g = lane >> 2;
    const int c = lane & 3;

    const int bm = blockIdx.y * GBM;
    const int bn = blockIdx.x * GBN;

    const int am  = tid >> 3;
    const int ak  = (tid & 7) << 2;
    const int bk  = tid >> 5;
    const int bn4 = (tid & 31) << 2;

    float acc[4][4][4];
#pragma unroll
    for (int mt = 0; mt < 4; ++mt)
#pragma unroll
        for (int nt = 0; nt < 4; ++nt)
#pragma unroll
            for (int r = 0; r < 4; ++r) acc[mt][nt][r] = 0.0f;

    const uint32_t sAs = (uint32_t)__cvta_generic_to_shared(As);
    const uint32_t sBs = (uint32_t)__cvta_generic_to_shared(Bs);

    auto load_tiles = [&](int buf, int kk) {
        const uint32_t a_base = sAs + buf * (GBM * AS_STRIDE * 4);
        const uint32_t b_base = sBs + buf * (GBK * BS_STRIDE * 4);
#pragma unroll
        for (int mm = 0; mm < GBM; mm += 32)
            cp_async16(a_base + ((am + mm) * AS_STRIDE + ak) * 4,
                       A + (size_t)(bm + am + mm) * K + kk + ak);
#pragma unroll
        for (int k2 = 0; k2 < GBK; k2 += 8)
            cp_async16(b_base + ((bk + k2) * BS_STRIDE + bn4) * 4,
                       Bg + (size_t)(kk + bk + k2) * N + bn + bn4);
        asm volatile("cp.async.commit_group;\n" ::);
    };

    const int NIT = K / GBK;
    load_tiles(0, 0);
    int buf = 0;

    for (int it = 0; it < NIT; ++it) {
        if (it + 1 < NIT) {
            load_tiles(buf ^ 1, (it + 1) * GBK);
            asm volatile("cp.async.wait_group 1;\n" ::);
        } else {
            asm volatile("cp.async.wait_group 0;\n" ::);
        }
        __syncthreads();

        const float* Ab = As + buf * GBM * AS_STRIDE;
        const float* Bb = Bs + buf * GBK * BS_STRIDE;

#pragma unroll
        for (int ks = 0; ks < 4; ++ks) {
            const int k0 = ks * 8;
            uint32_t af[4][4], bf[4][2];
#pragma unroll
            for (int mt = 0; mt < 4; ++mt) {
                const float* p0 = Ab + (rb + mt * 16 + g) * AS_STRIDE + k0 + c;
                const float* p1 = p0 + 8 * AS_STRIDE;
                af[mt][0] = __float_as_uint(p0[0]);
                af[mt][1] = __float_as_uint(p1[0]);
                af[mt][2] = __float_as_uint(p0[4]);
                af[mt][3] = __float_as_uint(p1[4]);
            }
#pragma unroll
            for (int nt = 0; nt < 4; ++nt) {
                const float* p = Bb + (k0 + c) * BS_STRIDE + nb + nt * 8 + g;
                bf[nt][0] = __float_as_uint(p[0]);
                bf[nt][1] = __float_as_uint(p[4 * BS_STRIDE]);
            }
#pragma unroll
            for (int mt = 0; mt < 4; ++mt)
#pragma unroll
                for (int nt = 0; nt < 4; ++nt)
                    mma_tf32(acc[mt][nt], af[mt], bf[nt]);
        }
        __syncthreads();
        buf ^= 1;
    }

#pragma unroll
    for (int mt = 0; mt < 4; ++mt) {
        const int row0 = bm + rb + mt * 16 + g;
#pragma unroll
        for (int nt = 0; nt < 4; ++nt) {
            const int col = bn + nb + nt * 8 + 2 * c;
            const float2 bv = *(const float2*)&bias[col];
            float2 o0 = { acc[mt][nt][0] + bv.x, acc[mt][nt][1] + bv.y };
            float2 o1 = { acc[mt][nt][2] + bv.x, acc[mt][nt][3] + bv.y };
            if (round_out) {
                o0.x = rna_tf32(o0.x); o0.y = rna_tf32(o0.y);
                o1.x = rna_tf32(o1.x); o1.y = rna_tf32(o1.y);
            }
            *(float2*)&C[(size_t)row0 * N + col] = o0;
            *(float2*)&C[(size_t)(row0 + 8) * N + col] = o1;
        }
    }
}

#define GEMM_SMEM ((2 * GBM * AS_STRIDE + 2 * GBK * BS_STRIDE) * 4)

// ============================================================================
// Tensor-core flash attention.
// CTA = one (b,h) x 128-query tile; 8 warps x 16 query rows each.
// S loop in 64-key chunks, cp.async double-buffered K/V.
// QK^T and PV via mma.sync tf32; softmax in log2 domain (ex2.approx).
// ============================================================================
#define SQ  128
#define SC  64
#define QST 100   // == 4 mod 32 -> conflict-free A-frag LDS (bank 4g+c)
#define KST 100   // == 4 mod 32
#define VST 104   // == 8 mod 32 -> conflict-free B-frag LDS (bank 8c+g)
#define PST 68    // == 4 mod 32

#define ATTN_SMEM ((SQ * QST + 2 * SC * KST + 2 * SC * VST + SQ * PST) * 4)

__global__ __launch_bounds__(256, 1)
void attn_tc()
{
    extern __shared__ float sm[];
    float* Qs = sm;                        // 128 x 100
    float* Ks = Qs + SQ * QST;             // 2 x 64 x 100
    float* Vs = Ks + 2 * SC * KST;         // 2 x 64 x 104
    float* Ps = Vs + 2 * SC * VST;         // 128 x 68

    const int tid  = threadIdx.x;
    const int w    = tid >> 5;
    const int lane = tid & 31;
    const int g = lane >> 2;
    const int c = lane & 3;
    const int bh = blockIdx.y;
    const int b = bh >> 3;
    const int h = bh & 7;
    const int q0 = blockIdx.x * SQ;
    const int r0 = w * 16 + g;             // this thread's first query row (tile-local)

    // fold 1/sqrt(96) * log2(e) into Q (softmax done base-2)
    const float qs = 0.1020620726159658f * 1.4426950408889634f;

    // Fill Q tile: scaled + rna-rounded
    for (int i = tid; i < SQ * (CE / 4); i += 256) {
        const int r = i / (CE / 4);
        const int c4 = (i % (CE / 4)) * 4;
        float4 v = *(const float4*)&g_Q[((size_t)(b * CL + q0 + r)) * CHE + h * CE + c4];
        Qs[r * QST + c4 + 0] = rna_tf32(v.x * qs);
        Qs[r * QST + c4 + 1] = rna_tf32(v.y * qs);
        Qs[r * QST + c4 + 2] = rna_tf32(v.z * qs);
        Qs[r * QST + c4 + 3] = rna_tf32(v.w * qs);
    }
    __syncthreads();

    // Hoist Q fragments (12 k-steps x 4 regs) for the whole S loop
    uint32_t qf[12][4];
#pragma unroll
    for (int ks = 0; ks < 12; ++ks) {
        const float* p = Qs + r0 * QST + ks * 8 + c;
        qf[ks][0] = __float_as_uint(p[0]);
        qf[ks][1] = __float_as_uint(p[8 * QST]);
        qf[ks][2] = __float_as_uint(p[4]);
        qf[ks][3] = __float_as_uint(p[8 * QST + 4]);
    }

    float oacc[12][4];
#pragma unroll
    for (int nt = 0; nt < 12; ++nt)
#pragma unroll
        for (int r = 0; r < 4; ++r) oacc[nt][r] = 0.0f;
    float m0 = -1e30f, m1 = -1e30f, l0 = 0.0f, l1 = 0.0f;

    const uint32_t sKs = (uint32_t)__cvta_generic_to_shared(Ks);
    const uint32_t sVs = (uint32_t)__cvta_generic_to_shared(Vs);

    auto load_kv = [&](int bufi, int s0) {
#pragma unroll
        for (int j = 0; j < 6; ++j) {
            const int idx = tid + j * 256;           // 0..1535
            const int r = idx / (CE / 4);
            const int c4 = (idx % (CE / 4)) * 4;
            const size_t off = ((size_t)(s0 + r)) * CHE + h * CE + c4;
            cp_async16(sKs + (bufi * SC * KST + r * KST + c4) * 4, &g_K[off]);
            cp_async16(sVs + (bufi * SC * VST + r * VST + c4) * 4, &g_V[off]);
        }
        asm volatile("cp.async.commit_group;\n" ::);
    };

    load_kv(0, 0);
    int buf = 0;

    for (int it = 0; it < CS / SC; ++it) {
        if (it + 1 < CS / SC) {
            load_kv(buf ^ 1, (it + 1) * SC);
            asm volatile("cp.async.wait_group 1;\n" ::);
        } else {
            asm volatile("cp.async.wait_group 0;\n" ::);
        }
        __syncthreads();

        const float* Kb = Ks + buf * SC * KST;
        const float* Vb = Vs + buf * SC * VST;

        // ---- QK^T: 16x64 scores per warp ----
        float sacc[8][4];
#pragma unroll
        for (int nt = 0; nt < 8; ++nt)
#pragma unroll
            for (int r = 0; r < 4; ++r) sacc[nt][r] = 0.0f;

#pragma unroll
        for (int ks = 0; ks < 12; ++ks) {
            uint32_t kf[8][2];
#pragma unroll
            for (int nt = 0; nt < 8; ++nt) {
                const float* p = Kb + (nt * 8 + g) * KST + ks * 8 + c;
                kf[nt][0] = __float_as_uint(p[0]);
                kf[nt][1] = __float_as_uint(p[4]);
            }
#pragma unroll
            for (int nt = 0; nt < 8; ++nt)
                mma_tf32(sacc[nt], qf[ks], kf[nt]);
        }

        // ---- online softmax (rows r0 and r0+8; quad-local reduction) ----
        float cm0 = -1e30f, cm1 = -1e30f;
#pragma unroll
        for (int nt = 0; nt < 8; ++nt) {
            cm0 = fmaxf(cm0, fmaxf(sacc[nt][0], sacc[nt][1]));
            cm1 = fmaxf(cm1, fmaxf(sacc[nt][2], sacc[nt][3]));
        }
        cm0 = fmaxf(cm0, __shfl_xor_sync(0xffffffffu, cm0, 1));
        cm0 = fmaxf(cm0, __shfl_xor_sync(0xffffffffu, cm0, 2));
        cm1 = fmaxf(cm1, __shfl_xor_sync(0xffffffffu, cm1, 1));
        cm1 = fmaxf(cm1, __shfl_xor_sync(0xffffffffu, cm1, 2));

        const float nm0 = fmaxf(m0, cm0);
        const float nm1 = fmaxf(m1, cm1);
        const float sc0 = ex2(m0 - nm0);
        const float sc1 = ex2(m1 - nm1);
        m0 = nm0; m1 = nm1;

        float rs0 = 0.0f, rs1 = 0.0f;
#pragma unroll
        for (int nt = 0; nt < 8; ++nt) {
            const float p00 = ex2(sacc[nt][0] - m0);
            const float p01 = ex2(sacc[nt][1] - m0);
            const float p10 = ex2(sacc[nt][2] - m1);
            const float p11 = ex2(sacc[nt][3] - m1);
            rs0 += p00 + p01;
            rs1 += p10 + p11;
            float* pr0 = Ps + r0 * PST + nt * 8 + 2 * c;
            pr0[0] = rna_tf32(p00);
            pr0[1] = rna_tf32(p01);
            float* pr1 = Ps + (r0 + 8) * PST + nt * 8 + 2 * c;
            pr1[0] = rna_tf32(p10);
            pr1[1] = rna_tf32(p11);
        }
        rs0 += __shfl_xor_sync(0xffffffffu, rs0, 1);
        rs0 += __shfl_xor_sync(0xffffffffu, rs0, 2);
        rs1 += __shfl_xor_sync(0xffffffffu, rs1, 1);
        rs1 += __shfl_xor_sync(0xffffffffu, rs1, 2);
        l0 = l0 * sc0 + rs0;
        l1 = l1 * sc1 + rs1;

#pragma unroll
        for (int nt = 0; nt < 12; ++nt) {
            oacc[nt][0] *= sc0; oacc[nt][1] *= sc0;
            oacc[nt][2] *= sc1; oacc[nt][3] *= sc1;
        }
        __syncwarp();

        // ---- PV: O[16 x 96] += P[16 x 64] @ V[64 x 96] ----
#pragma unroll
        for (int ks = 0; ks < 8; ++ks) {
            uint32_t pf[4];
            const float* pp = Ps + r0 * PST + ks * 8 + c;
            pf[0] = __float_as_uint(pp[0]);
            pf[1] = __float_as_uint(pp[8 * PST]);
            pf[2] = __float_as_uint(pp[4]);
            pf[3] = __float_as_uint(pp[8 * PST + 4]);
#pragma unroll
            for (int nt = 0; nt < 12; ++nt) {
                const float* vp = Vb + (ks * 8 + c) * VST + nt * 8 + g;
                uint32_t vf[2];
                vf[0] = __float_as_uint(vp[0]);
                vf[1] = __float_as_uint(vp[4 * VST]);
                mma_tf32(oacc[nt], pf, vf);
            }
        }
        __syncthreads();
        buf ^= 1;
    }

    // ---- epilogue: normalize, rna-round (feeds out-proj GEMM), store ----
    const float inv0 = 1.0f / l0;
    const float inv1 = 1.0f / l1;
    const size_t row0 = ((size_t)(b * CL + q0 + r0)) * CHE + h * CE;
    const size_t row1 = ((size_t)(b * CL + q0 + r0 + 8)) * CHE + h * CE;
#pragma unroll
    for (int nt = 0; nt < 12; ++nt) {
        const int col = nt * 8 + 2 * c;
        float2 o0 = { rna_tf32(oacc[nt][0] * inv0), rna_tf32(oacc[nt][1] * inv0) };
        float2 o1 = { rna_tf32(oacc[nt][2] * inv1), rna_tf32(oacc[nt][3] * inv1) };
        *(float2*)&g_rep[row0 + col] = o0;
        *(float2*)&g_rep[row1 + col] = o1;
    }
}

// ============================================================================
// Launch
// ============================================================================
extern "C" void kernel_launch(void* const* d_in, const int* in_sizes, int n_in,
                              void* d_out, int out_size)
{
    const float* target = (const float*)d_in[0];
    const float* source = (const float*)d_in[1];
    const float* Wq = (const float*)d_in[2];
    const float* bq = (const float*)d_in[3];
    const float* Wk = (const float*)d_in[4];
    const float* bk = (const float*)d_in[5];
    const float* Wv = (const float*)d_in[6];
    const float* bv = (const float*)d_in[7];
    const float* Wo = (const float*)d_in[8];
    const float* bo = (const float*)d_in[9];
    float* out = (float*)d_out;

    float *Qp, *Kp, *Vp, *Rp, *Tp, *Sp, *Wqp, *Wkp, *Wvp, *Wop;
    cudaGetSymbolAddress((void**)&Qp, g_Q);
    cudaGetSymbolAddress((void**)&Kp, g_K);
    cudaGetSymbolAddress((void**)&Vp, g_V);
    cudaGetSymbolAddress((void**)&Rp, g_rep);
    cudaGetSymbolAddress((void**)&Tp, g_tgt);
    cudaGetSymbolAddress((void**)&Sp, g_src);
    cudaGetSymbolAddress((void**)&Wqp, g_wq);
    cudaGetSymbolAddress((void**)&Wkp, g_wk);
    cudaGetSymbolAddress((void**)&Wvp, g_wv);
    cudaGetSymbolAddress((void**)&Wop, g_wo);

    cudaFuncSetAttribute(gemm_tf32, cudaFuncAttributeMaxDynamicSharedMemorySize,
                         GEMM_SMEM);
    cudaFuncSetAttribute(attn_tc, cudaFuncAttributeMaxDynamicSharedMemorySize,
                         ATTN_SMEM);

    const dim3 blk(256);

    // Pre-round GEMM inputs to tf32 (rna)
    auto rr = [&](const float* s, float* d, int n) {
        const int n4 = n / 4;
        round_tf32_kernel<<<(n4 + 255) / 256, 256>>>((const float4*)s, (float4*)d, n4);
    };
    rr(target, Tp, CB * CL * CDM);
    rr(source, Sp, CS * CDL);
    rr(Wq, Wqp, CDM * CHE);
    rr(Wk, Wkp, CDL * CHE);
    rr(Wv, Wvp, CDL * CHE);
    rr(Wo, Wop, CHE * CDL);

    // Q = target @ Wq + bq   (8192 x 768, K=768), rounded for attention
    gemm_tf32<<<dim3(CHE / GBN, (CB * CL) / GBM, 1), blk, GEMM_SMEM>>>(
        Tp, Wqp, bq, Qp, Wqp, bq, Qp, CB * CL, CHE, CDM, 1);

    // K and V projections fused via blockIdx.z (2048 x 768, K=4096), rounded
    gemm_tf32<<<dim3(CHE / GBN, CS / GBM, 2), blk, GEMM_SMEM>>>(
        Sp, Wkp, bk, Kp, Wvp, bv, Vp, CS, CHE, CDL, 1);

    // Attention -> rep (tensor-core, rounded epilogue)
    attn_tc<<<dim3(CL / SQ, CB * CH), blk, ATTN_SMEM>>>();

    // out = rep @ Wo + bo   (8192 x 4096, K=768), full fp32 epilogue
    gemm_tf32<<<dim3(CDL / GBN, (CB * CL) / GBM, 1), blk, GEMM_SMEM>>>(
        Rp, Wop, bo, out, Wop, bo, out, CB * CL, CDL, CHE, 0);
}

// round 8
// speedup vs baseline: 5.5302x; 1.0732x over previous
#include <cuda_runtime.h>
#include <math_constants.h>
#include <stdint.h>

// Problem constants
#define CB   16
#define CL   512
#define CDM  768
#define CS   2048
#define CDL  4096
#define CH   8
#define CE   96
#define CHE  768   // H*E

// Scratch (allocation-free: device globals)
__device__ float g_Q[(size_t)CB * CL * CHE];   // 8192 x 768 (tf32-rounded)
__device__ float g_K[(size_t)CS * CHE];        // 2048 x 768 (tf32-rounded)
__device__ float g_V[(size_t)CS * CHE];        // 2048 x 768 (tf32-rounded)
__device__ float g_rep[(size_t)CB * CL * CHE]; // 8192 x 768 (tf32-rounded)
// Pre-rounded copies of GEMM inputs (low 13 mantissa bits zeroed, rna)
__device__ float g_tgt[(size_t)CB * CL * CDM];
__device__ float g_src[(size_t)CS * CDL];
__device__ float g_wq[(size_t)CDM * CHE];
__device__ float g_wk[(size_t)CDL * CHE];
__device__ float g_wv[(size_t)CDL * CHE];
__device__ float g_wo[(size_t)CHE * CDL];
// Split-K partials for K/V projections: z in [0,8): (split = z>>1, K/V = z&1)
__device__ float g_kvpart[(size_t)8 * CS * CHE];   // 48 MB

__device__ __forceinline__ float rna_tf32(float x) {
    uint32_t r;
    asm("cvt.rna.tf32.f32 %0, %1;" : "=r"(r) : "f"(x));
    return __uint_as_float(r);
}

__device__ __forceinline__ float ex2(float x) {
    float y;
    asm("ex2.approx.f32 %0, %1;" : "=f"(y) : "f"(x));
    return y;
}

__device__ __forceinline__ void mma_tf32(float* d, const uint32_t* a, const uint32_t* b) {
    asm volatile(
        "mma.sync.aligned.m16n8k8.row.col.f32.tf32.tf32.f32 "
        "{%0,%1,%2,%3}, {%4,%5,%6,%7}, {%8,%9}, {%0,%1,%2,%3};"
        : "+f"(d[0]), "+f"(d[1]), "+f"(d[2]), "+f"(d[3])
        : "r"(a[0]), "r"(a[1]), "r"(a[2]), "r"(a[3]), "r"(b[0]), "r"(b[1]));
}

__device__ __forceinline__ void cp_async16(uint32_t dst, const void* src) {
    asm volatile("cp.async.cg.shared.global [%0], [%1], 16;\n" :: "r"(dst), "l"(src));
}

// ============================================================================
// Elementwise tf32 pre-round (rna)
// ============================================================================
__global__ void round_tf32_kernel(const float4* __restrict__ src,
                                  float4* __restrict__ dst, int n4)
{
    int i = blockIdx.x * blockDim.x + threadIdx.x;
    if (i < n4) {
        float4 v = src[i];
        v.x = rna_tf32(v.x); v.y = rna_tf32(v.y);
        v.z = rna_tf32(v.z); v.w = rna_tf32(v.w);
        dst[i] = v;
    }
}

// ============================================================================
// TF32 mma.sync GEMM, 3-stage cp.async pipeline.
// C[M,N] = A[M,K] @ B[K,N] + bias[N]; optionally rna-round outputs.
// 128x128x32 tile, 256 threads = 8 warps (2Mx4N), warp tile 64x32.
// If gridDim.z==2, blockIdx.z selects (B0,bias0,C0) vs (B1,bias1,C1).
// ============================================================================
#define GBM 128
#define GBN 128
#define GBK 32
#define AS_STRIDE 36
#define BS_STRIDE 136
#define AS_ELEMS (GBM * AS_STRIDE)
#define BS_ELEMS (GBK * BS_STRIDE)
#define GEMM_SMEM (3 * (AS_ELEMS + BS_ELEMS) * 4)

struct GemmCtx {
    int tid, rb, nb, g, c, am, ak, bk, bn4;
};

__device__ __forceinline__ void gemm_core(
    const float* __restrict__ A, const float* __restrict__ Bg,
    int bm, int bn, int N, int K, int k_begin, int k_len,
    float* As, float* Bs, float acc[4][4][4], const GemmCtx& x)
{
    const uint32_t sAs = (uint32_t)__cvta_generic_to_shared(As);
    const uint32_t sBs = (uint32_t)__cvta_generic_to_shared(Bs);

    auto load_tiles = [&](int stg, int kk) {
        const uint32_t a_base = sAs + stg * (AS_ELEMS * 4);
        const uint32_t b_base = sBs + stg * (BS_ELEMS * 4);
#pragma unroll
        for (int mm = 0; mm < GBM; mm += 32)
            cp_async16(a_base + ((x.am + mm) * AS_STRIDE + x.ak) * 4,
                       A + (size_t)(bm + x.am + mm) * K + kk + x.ak);
#pragma unroll
        for (int k2 = 0; k2 < GBK; k2 += 8)
            cp_async16(b_base + ((x.bk + k2) * BS_STRIDE + x.bn4) * 4,
                       Bg + (size_t)(kk + x.bk + k2) * N + bn + x.bn4);
        asm volatile("cp.async.commit_group;\n" ::);
    };

    const int NC = k_len / GBK;
    load_tiles(0, k_begin);
    load_tiles(1, k_begin + GBK);

    for (int i = 0; i < NC; ++i) {
        if (i + 1 < NC) asm volatile("cp.async.wait_group 1;\n" ::);
        else            asm volatile("cp.async.wait_group 0;\n" ::);
        __syncthreads();
        if (i + 2 < NC)
            load_tiles((i + 2) % 3, k_begin + (i + 2) * GBK);

        const float* Ab = As + (i % 3) * AS_ELEMS;
        const float* Bb = Bs + (i % 3) * BS_ELEMS;

#pragma unroll
        for (int ks = 0; ks < 4; ++ks) {
            const int k0 = ks * 8;
            uint32_t af[4][4], bf[4][2];
#pragma unroll
            for (int mt = 0; mt < 4; ++mt) {
                const float* p0 = Ab + (x.rb + mt * 16 + x.g) * AS_STRIDE + k0 + x.c;
                const float* p1 = p0 + 8 * AS_STRIDE;
                af[mt][0] = __float_as_uint(p0[0]);
                af[mt][1] = __float_as_uint(p1[0]);
                af[mt][2] = __float_as_uint(p0[4]);
                af[mt][3] = __float_as_uint(p1[4]);
            }
#pragma unroll
            for (int nt = 0; nt < 4; ++nt) {
                const float* p = Bb + (k0 + x.c) * BS_STRIDE + x.nb + nt * 8 + x.g;
                bf[nt][0] = __float_as_uint(p[0]);
                bf[nt][1] = __float_as_uint(p[4 * BS_STRIDE]);
            }
#pragma unroll
            for (int mt = 0; mt < 4; ++mt)
#pragma unroll
                for (int nt = 0; nt < 4; ++nt)
                    mma_tf32(acc[mt][nt], af[mt], bf[nt]);
        }
    }
}

__device__ __forceinline__ void gemm_ctx_init(GemmCtx& x) {
    const int tid = threadIdx.x;
    const int wid = tid >> 5;
    const int lane = tid & 31;
    x.tid = tid;
    x.rb = (wid & 1) * 64;
    x.nb = (wid >> 1) * 32;
    x.g = lane >> 2;
    x.c = lane & 3;
    x.am = tid >> 3;
    x.ak = (tid & 7) << 2;
    x.bk = tid >> 5;
    x.bn4 = (tid & 31) << 2;
}

__global__ __launch_bounds__(256, 2)
void gemm_tf32(const float* __restrict__ A,
               const float* __restrict__ B0, const float* __restrict__ bias0,
               float* __restrict__ C0,
               const float* __restrict__ B1, const float* __restrict__ bias1,
               float* __restrict__ C1,
               int M, int N, int K, int round_out)
{
    extern __shared__ float smem[];
    const float* Bg   = (blockIdx.z == 0) ? B0 : B1;
    const float* bias = (blockIdx.z == 0) ? bias0 : bias1;
    float*       C    = (blockIdx.z == 0) ? C0 : C1;

    GemmCtx x; gemm_ctx_init(x);
    const int bm = blockIdx.y * GBM;
    const int bn = blockIdx.x * GBN;

    float acc[4][4][4];
#pragma unroll
    for (int mt = 0; mt < 4; ++mt)
#pragma unroll
        for (int nt = 0; nt < 4; ++nt)
#pragma unroll
            for (int r = 0; r < 4; ++r) acc[mt][nt][r] = 0.0f;

    gemm_core(A, Bg, bm, bn, N, K, 0, K, smem, smem + 3 * AS_ELEMS, acc, x);

#pragma unroll
    for (int mt = 0; mt < 4; ++mt) {
        const int row0 = bm + x.rb + mt * 16 + x.g;
#pragma unroll
        for (int nt = 0; nt < 4; ++nt) {
            const int col = bn + x.nb + nt * 8 + 2 * x.c;
            const float2 bv = *(const float2*)&bias[col];
            float2 o0 = { acc[mt][nt][0] + bv.x, acc[mt][nt][1] + bv.y };
            float2 o1 = { acc[mt][nt][2] + bv.x, acc[mt][nt][3] + bv.y };
            if (round_out) {
                o0.x = rna_tf32(o0.x); o0.y = rna_tf32(o0.y);
                o1.x = rna_tf32(o1.x); o1.y = rna_tf32(o1.y);
            }
            *(float2*)&C[(size_t)row0 * N + col] = o0;
            *(float2*)&C[(size_t)(row0 + 8) * N + col] = o1;
        }
    }
}

// Split-K GEMM for K/V projections: z = (split<<1) | (isV).
// Each CTA computes a 128x128 tile over K range [split*1024, +1024), raw store.
__global__ __launch_bounds__(256, 2)
void gemm_tf32_sk(const float* __restrict__ A,
                  const float* __restrict__ Bk, const float* __restrict__ Bv,
                  float* __restrict__ Cpart, int M, int N, int K)
{
    extern __shared__ float smem[];
    const int z = blockIdx.z;
    const float* Bg = (z & 1) ? Bv : Bk;
    const int split = z >> 1;
    float* C = Cpart + (size_t)z * M * N;

    GemmCtx x; gemm_ctx_init(x);
    const int bm = blockIdx.y * GBM;
    const int bn = blockIdx.x * GBN;

    float acc[4][4][4];
#pragma unroll
    for (int mt = 0; mt < 4; ++mt)
#pragma unroll
        for (int nt = 0; nt < 4; ++nt)
#pragma unroll
            for (int r = 0; r < 4; ++r) acc[mt][nt][r] = 0.0f;

    gemm_core(A, Bg, bm, bn, N, K, split * (K / 4), K / 4,
              smem, smem + 3 * AS_ELEMS, acc, x);

#pragma unroll
    for (int mt = 0; mt < 4; ++mt) {
        const int row0 = bm + x.rb + mt * 16 + x.g;
#pragma unroll
        for (int nt = 0; nt < 4; ++nt) {
            const int col = bn + x.nb + nt * 8 + 2 * x.c;
            *(float2*)&C[(size_t)row0 * N + col] =
                make_float2(acc[mt][nt][0], acc[mt][nt][1]);
            *(float2*)&C[(size_t)(row0 + 8) * N + col] =
                make_float2(acc[mt][nt][2], acc[mt][nt][3]);
        }
    }
}

// Reduce the 4 split-K partials for K and V, add bias, rna-round.
__global__ void reduce_kv(const float* __restrict__ part,
                          const float* __restrict__ bk, const float* __restrict__ bv,
                          float* __restrict__ Kout, float* __restrict__ Vout)
{
    const int i4 = blockIdx.x * blockDim.x + threadIdx.x;
    const int n4 = CS * CHE / 4;
    if (i4 >= n4) return;
    const size_t MN = (size_t)CS * CHE;
    const size_t off = (size_t)i4 * 4;
    const int col = (int)(off % CHE);

    float4 sk = make_float4(0.f, 0.f, 0.f, 0.f);
    float4 sv = make_float4(0.f, 0.f, 0.f, 0.f);
#pragma unroll
    for (int s = 0; s < 4; ++s) {
        float4 pk = *(const float4*)&part[(size_t)(2 * s) * MN + off];
        float4 pv = *(const float4*)&part[(size_t)(2 * s + 1) * MN + off];
        sk.x += pk.x; sk.y += pk.y; sk.z += pk.z; sk.w += pk.w;
        sv.x += pv.x; sv.y += pv.y; sv.z += pv.z; sv.w += pv.w;
    }
    float4 bkv = *(const float4*)&bk[col];
    float4 bvv = *(const float4*)&bv[col];
    float4 ok = { rna_tf32(sk.x + bkv.x), rna_tf32(sk.y + bkv.y),
                  rna_tf32(sk.z + bkv.z), rna_tf32(sk.w + bkv.w) };
    float4 ov = { rna_tf32(sv.x + bvv.x), rna_tf32(sv.y + bvv.y),
                  rna_tf32(sv.z + bvv.z), rna_tf32(sv.w + bvv.w) };
    *(float4*)&Kout[off] = ok;
    *(float4*)&Vout[off] = ov;
}

// ============================================================================
// Tensor-core flash attention (unchanged from R4).
// ============================================================================
#define SQ  128
#define SC  64
#define QST 100
#define KST 100
#define VST 104
#define PST 68

#define ATTN_SMEM ((SQ * QST + 2 * SC * KST + 2 * SC * VST + SQ * PST) * 4)

__global__ __launch_bounds__(256, 1)
void attn_tc()
{
    extern __shared__ float sm[];
    float* Qs = sm;
    float* Ks = Qs + SQ * QST;
    float* Vs = Ks + 2 * SC * KST;
    float* Ps = Vs + 2 * SC * VST;

    const int tid  = threadIdx.x;
    const int w    = tid >> 5;
    const int lane = tid & 31;
    const int g = lane >> 2;
    const int c = lane & 3;
    const int bh = blockIdx.y;
    const int b = bh >> 3;
    const int h = bh & 7;
    const int q0 = blockIdx.x * SQ;
    const int r0 = w * 16 + g;

    const float qs = 0.1020620726159658f * 1.4426950408889634f;

    for (int i = tid; i < SQ * (CE / 4); i += 256) {
        const int r = i / (CE / 4);
        const int c4 = (i % (CE / 4)) * 4;
        float4 v = *(const float4*)&g_Q[((size_t)(b * CL + q0 + r)) * CHE + h * CE + c4];
        Qs[r * QST + c4 + 0] = rna_tf32(v.x * qs);
        Qs[r * QST + c4 + 1] = rna_tf32(v.y * qs);
        Qs[r * QST + c4 + 2] = rna_tf32(v.z * qs);
        Qs[r * QST + c4 + 3] = rna_tf32(v.w * qs);
    }
    __syncthreads();

    uint32_t qf[12][4];
#pragma unroll
    for (int ks = 0; ks < 12; ++ks) {
        const float* p = Qs + r0 * QST + ks * 8 + c;
        qf[ks][0] = __float_as_uint(p[0]);
        qf[ks][1] = __float_as_uint(p[8 * QST]);
        qf[ks][2] = __float_as_uint(p[4]);
        qf[ks][3] = __float_as_uint(p[8 * QST + 4]);
    }

    float oacc[12][4];
#pragma unroll
    for (int nt = 0; nt < 12; ++nt)
#pragma unroll
        for (int r = 0; r < 4; ++r) oacc[nt][r] = 0.0f;
    float m0 = -1e30f, m1 = -1e30f, l0 = 0.0f, l1 = 0.0f;

    const uint32_t sKs = (uint32_t)__cvta_generic_to_shared(Ks);
    const uint32_t sVs = (uint32_t)__cvta_generic_to_shared(Vs);

    auto load_kv = [&](int bufi, int s0) {
#pragma unroll
        for (int j = 0; j < 6; ++j) {
            const int idx = tid + j * 256;
            const int r = idx / (CE / 4);
            const int c4 = (idx % (CE / 4)) * 4;
            const size_t off = ((size_t)(s0 + r)) * CHE + h * CE + c4;
            cp_async16(sKs + (bufi * SC * KST + r * KST + c4) * 4, &g_K[off]);
            cp_async16(sVs + (bufi * SC * VST + r * VST + c4) * 4, &g_V[off]);
        }
        asm volatile("cp.async.commit_group;\n" ::);
    };

    load_kv(0, 0);
    int buf = 0;

    for (int it = 0; it < CS / SC; ++it) {
        if (it + 1 < CS / SC) {
            load_kv(buf ^ 1, (it + 1) * SC);
            asm volatile("cp.async.wait_group 1;\n" ::);
        } else {
            asm volatile("cp.async.wait_group 0;\n" ::);
        }
        __syncthreads();

        const float* Kb = Ks + buf * SC * KST;
        const float* Vb = Vs + buf * SC * VST;

        float sacc[8][4];
#pragma unroll
        for (int nt = 0; nt < 8; ++nt)
#pragma unroll
            for (int r = 0; r < 4; ++r) sacc[nt][r] = 0.0f;

#pragma unroll
        for (int ks = 0; ks < 12; ++ks) {
            uint32_t kf[8][2];
#pragma unroll
            for (int nt = 0; nt < 8; ++nt) {
                const float* p = Kb + (nt * 8 + g) * KST + ks * 8 + c;
                kf[nt][0] = __float_as_uint(p[0]);
                kf[nt][1] = __float_as_uint(p[4]);
            }
#pragma unroll
            for (int nt = 0; nt < 8; ++nt)
                mma_tf32(sacc[nt], qf[ks], kf[nt]);
        }

        float cm0 = -1e30f, cm1 = -1e30f;
#pragma unroll
        for (int nt = 0; nt < 8; ++nt) {
            cm0 = fmaxf(cm0, fmaxf(sacc[nt][0], sacc[nt][1]));
            cm1 = fmaxf(cm1, fmaxf(sacc[nt][2], sacc[nt][3]));
        }
        cm0 = fmaxf(cm0, __shfl_xor_sync(0xffffffffu, cm0, 1));
        cm0 = fmaxf(cm0, __shfl_xor_sync(0xffffffffu, cm0, 2));
        cm1 = fmaxf(cm1, __shfl_xor_sync(0xffffffffu, cm1, 1));
        cm1 = fmaxf(cm1, __shfl_xor_sync(0xffffffffu, cm1, 2));

        const float nm0 = fmaxf(m0, cm0);
        const float nm1 = fmaxf(m1, cm1);
        const float sc0 = ex2(m0 - nm0);
        const float sc1 = ex2(m1 - nm1);
        m0 = nm0; m1 = nm1;

        float rs0 = 0.0f, rs1 = 0.0f;
#pragma unroll
        for (int nt = 0; nt < 8; ++nt) {
            const float p00 = ex2(sacc[nt][0] - m0);
            const float p01 = ex2(sacc[nt][1] - m0);
            const float p10 = ex2(sacc[nt][2] - m1);
            const float p11 = ex2(sacc[nt][3] - m1);
            rs0 += p00 + p01;
            rs1 += p10 + p11;
            float* pr0 = Ps + r0 * PST + nt * 8 + 2 * c;
            pr0[0] = rna_tf32(p00);
            pr0[1] = rna_tf32(p01);
            float* pr1 = Ps + (r0 + 8) * PST + nt * 8 + 2 * c;
            pr1[0] = rna_tf32(p10);
            pr1[1] = rna_tf32(p11);
        }
        rs0 += __shfl_xor_sync(0xffffffffu, rs0, 1);
        rs0 += __shfl_xor_sync(0xffffffffu, rs0, 2);
        rs1 += __shfl_xor_sync(0xffffffffu, rs1, 1);
        rs1 += __shfl_xor_sync(0xffffffffu, rs1, 2);
        l0 = l0 * sc0 + rs0;
        l1 = l1 * sc1 + rs1;

#pragma unroll
        for (int nt = 0; nt < 12; ++nt) {
            oacc[nt][0] *= sc0; oacc[nt][1] *= sc0;
            oacc[nt][2] *= sc1; oacc[nt][3] *= sc1;
        }
        __syncwarp();

#pragma unroll
        for (int ks = 0; ks < 8; ++ks) {
            uint32_t pf[4];
            const float* pp = Ps + r0 * PST + ks * 8 + c;
            pf[0] = __float_as_uint(pp[0]);
            pf[1] = __float_as_uint(pp[8 * PST]);
            pf[2] = __float_as_uint(pp[4]);
            pf[3] = __float_as_uint(pp[8 * PST + 4]);
#pragma unroll
            for (int nt = 0; nt < 12; ++nt) {
                const float* vp = Vb + (ks * 8 + c) * VST + nt * 8 + g;
                uint32_t vf[2];
                vf[0] = __float_as_uint(vp[0]);
                vf[1] = __float_as_uint(vp[4 * VST]);
                mma_tf32(oacc[nt], pf, vf);
            }
        }
        __syncthreads();
        buf ^= 1;
    }

    const float inv0 = 1.0f / l0;
    const float inv1 = 1.0f / l1;
    const size_t row0 = ((size_t)(b * CL + q0 + r0)) * CHE + h * CE;
    const size_t row1 = ((size_t)(b * CL + q0 + r0 + 8)) * CHE + h * CE;
#pragma unroll
    for (int nt = 0; nt < 12; ++nt) {
        const int col = nt * 8 + 2 * c;
        float2 o0 = { rna_tf32(oacc[nt][0] * inv0), rna_tf32(oacc[nt][1] * inv0) };
        float2 o1 = { rna_tf32(oacc[nt][2] * inv1), rna_tf32(oacc[nt][3] * inv1) };
        *(float2*)&g_rep[row0 + col] = o0;
        *(float2*)&g_rep[row1 + col] = o1;
    }
}

// ============================================================================
// Launch
// ============================================================================
extern "C" void kernel_launch(void* const* d_in, const int* in_sizes, int n_in,
                              void* d_out, int out_size)
{
    const float* target = (const float*)d_in[0];
    const float* source = (const float*)d_in[1];
    const float* Wq = (const float*)d_in[2];
    const float* bq = (const float*)d_in[3];
    const float* Wk = (const float*)d_in[4];
    const float* bk = (const float*)d_in[5];
    const float* Wv = (const float*)d_in[6];
    const float* bv = (const float*)d_in[7];
    const float* Wo = (const float*)d_in[8];
    const float* bo = (const float*)d_in[9];
    float* out = (float*)d_out;

    float *Qp, *Kp, *Vp, *Rp, *Tp, *Sp, *Wqp, *Wkp, *Wvp, *Wop, *Pp;
    cudaGetSymbolAddress((void**)&Qp, g_Q);
    cudaGetSymbolAddress((void**)&Kp, g_K);
    cudaGetSymbolAddress((void**)&Vp, g_V);
    cudaGetSymbolAddress((void**)&Rp, g_rep);
    cudaGetSymbolAddress((void**)&Tp, g_tgt);
    cudaGetSymbolAddress((void**)&Sp, g_src);
    cudaGetSymbolAddress((void**)&Wqp, g_wq);
    cudaGetSymbolAddress((void**)&Wkp, g_wk);
    cudaGetSymbolAddress((void**)&Wvp, g_wv);
    cudaGetSymbolAddress((void**)&Wop, g_wo);
    cudaGetSymbolAddress((void**)&Pp, g_kvpart);

    cudaFuncSetAttribute(gemm_tf32, cudaFuncAttributeMaxDynamicSharedMemorySize,
                         GEMM_SMEM);
    cudaFuncSetAttribute(gemm_tf32_sk, cudaFuncAttributeMaxDynamicSharedMemorySize,
                         GEMM_SMEM);
    cudaFuncSetAttribute(attn_tc, cudaFuncAttributeMaxDynamicSharedMemorySize,
                         ATTN_SMEM);

    const dim3 blk(256);

    // Pre-round GEMM inputs to tf32 (rna)
    auto rr = [&](const float* s, float* d, int n) {
        const int n4 = n / 4;
        round_tf32_kernel<<<(n4 + 255) / 256, 256>>>((const float4*)s, (float4*)d, n4);
    };
    rr(target, Tp, CB * CL * CDM);
    rr(source, Sp, CS * CDL);
    rr(Wq, Wqp, CDM * CHE);
    rr(Wk, Wkp, CDL * CHE);
    rr(Wv, Wvp, CDL * CHE);
    rr(Wo, Wop, CHE * CDL);

    // Q = target @ Wq + bq   (8192 x 768, K=768), rounded for attention
    gemm_tf32<<<dim3(CHE / GBN, (CB * CL) / GBM, 1), blk, GEMM_SMEM>>>(
        Tp, Wqp, bq, Qp, Wqp, bq, Qp, CB * CL, CHE, CDM, 1);

    // K and V projections: split-K x4 partials (z = split*2 + isV), then reduce
    gemm_tf32_sk<<<dim3(CHE / GBN, CS / GBM, 8), blk, GEMM_SMEM>>>(
        Sp, Wkp, Wvp, Pp, CS, CHE, CDL);
    {
        const int n4 = CS * CHE / 4;
        reduce_kv<<<(n4 + 255) / 256, 256>>>(Pp, bk, bv, Kp, Vp);
    }

    // Attention -> rep (tensor-core, rounded epilogue)
    attn_tc<<<dim3(CL / SQ, CB * CH), blk, ATTN_SMEM>>>();

    // out = rep @ Wo + bo   (8192 x 4096, K=768), full fp32 epilogue
    gemm_tf32<<<dim3(CDL / GBN, (CB * CL) / GBM, 1), blk, GEMM_SMEM>>>(
        Rp, Wop, bo, out, Wop, bo, out, CB * CL, CDL, CHE, 0);
}

// round 9
// speedup vs baseline: 5.7304x; 1.0362x over previous
#include <cuda_runtime.h>
#include <math_constants.h>
#include <stdint.h>

// Problem constants
#define CB   16
#define CL   512
#define CDM  768
#define CS   2048
#define CDL  4096
#define CH   8
#define CE   96
#define CHE  768   // H*E

// Scratch (allocation-free: device globals)
__device__ float g_Q[(size_t)CB * CL * CHE];   // 8192 x 768 (tf32-rounded)
__device__ float g_K[(size_t)CS * CHE];        // 2048 x 768 (tf32-rounded)
__device__ float g_V[(size_t)CS * CHE];        // 2048 x 768 (tf32-rounded)
__device__ float g_rep[(size_t)CB * CL * CHE]; // 8192 x 768 (tf32-rounded)
// Pre-rounded copies of GEMM inputs (low 13 mantissa bits zeroed, rna)
__device__ float g_tgt[(size_t)CB * CL * CDM];
__device__ float g_src[(size_t)CS * CDL];
__device__ float g_wq[(size_t)CDM * CHE];
__device__ float g_wk[(size_t)CDL * CHE];
__device__ float g_wv[(size_t)CDL * CHE];
__device__ float g_wo[(size_t)CHE * CDL];
// Split-K partials for K/V projections: z in [0,8): (split = z>>1, K/V = z&1)
__device__ float g_kvpart[(size_t)8 * CS * CHE];   // 48 MB

__device__ __forceinline__ float rna_tf32(float x) {
    uint32_t r;
    asm("cvt.rna.tf32.f32 %0, %1;" : "=r"(r) : "f"(x));
    return __uint_as_float(r);
}

__device__ __forceinline__ float ex2(float x) {
    float y;
    asm("ex2.approx.f32 %0, %1;" : "=f"(y) : "f"(x));
    return y;
}

__device__ __forceinline__ void mma_tf32(float* d, const uint32_t* a, const uint32_t* b) {
    asm volatile(
        "mma.sync.aligned.m16n8k8.row.col.f32.tf32.tf32.f32 "
        "{%0,%1,%2,%3}, {%4,%5,%6,%7}, {%8,%9}, {%0,%1,%2,%3};"
        : "+f"(d[0]), "+f"(d[1]), "+f"(d[2]), "+f"(d[3])
        : "r"(a[0]), "r"(a[1]), "r"(a[2]), "r"(a[3]), "r"(b[0]), "r"(b[1]));
}

__device__ __forceinline__ void cp_async16(uint32_t dst, const void* src) {
    asm volatile("cp.async.cg.shared.global [%0], [%1], 16;\n" :: "r"(dst), "l"(src));
}

// ============================================================================
// Elementwise tf32 pre-round (rna)
// ============================================================================
__global__ void round_tf32_kernel(const float4* __restrict__ src,
                                  float4* __restrict__ dst, int n4)
{
    int i = blockIdx.x * blockDim.x + threadIdx.x;
    if (i < n4) {
        float4 v = src[i];
        v.x = rna_tf32(v.x); v.y = rna_tf32(v.y);
        v.z = rna_tf32(v.z); v.w = rna_tf32(v.w);
        dst[i] = v;
    }
}

// ============================================================================
// TF32 mma.sync GEMM core, 64x64 warp tiles (crossbar-balanced).
// 128x128x32 block tile, 128 threads = 4 warps (2Mx2N), 3-stage cp.async.
// ============================================================================
#define GBM 128
#define GBN 128
#define GBK 32
#define AS_STRIDE 36
#define BS_STRIDE 136
#define AS_ELEMS (GBM * AS_STRIDE)
#define BS_ELEMS (GBK * BS_STRIDE)
#define GEMM_SMEM (3 * (AS_ELEMS + BS_ELEMS) * 4)

struct GemmCtx { int tid, rb, nb, g, c; };

__device__ __forceinline__ void gemm_ctx_init(GemmCtx& x) {
    const int tid = threadIdx.x;
    const int wid = tid >> 5;
    const int lane = tid & 31;
    x.tid = tid;
    x.rb = (wid & 1) * 64;
    x.nb = (wid >> 1) * 64;
    x.g = lane >> 2;
    x.c = lane & 3;
}

// acc[4][8][4]: mt over 4 m16 tiles, nt over 8 n8 tiles
__device__ __forceinline__ void gemm_core(
    const float* __restrict__ A, const float* __restrict__ Bg,
    int bm, int bn, int N, int K, int k_begin, int k_len,
    float* As, float* Bs, float acc[4][8][4], const GemmCtx& x)
{
    const uint32_t sAs = (uint32_t)__cvta_generic_to_shared(As);
    const uint32_t sBs = (uint32_t)__cvta_generic_to_shared(Bs);
    const int tid = x.tid;

    auto load_tiles = [&](int stg, int kk) {
        const uint32_t a_base = sAs + stg * (AS_ELEMS * 4);
        const uint32_t b_base = sBs + stg * (BS_ELEMS * 4);
#pragma unroll
        for (int j = 0; j < 8; ++j) {
            const int idx = tid + j * 128;          // 0..1023
            const int rA = idx >> 3;                // 0..127
            const int cA = (idx & 7) << 2;          // 0..28
            cp_async16(a_base + (rA * AS_STRIDE + cA) * 4,
                       A + (size_t)(bm + rA) * K + kk + cA);
            const int rB = idx >> 5;                // 0..31
            const int cB = (idx & 31) << 2;         // 0..124
            cp_async16(b_base + (rB * BS_STRIDE + cB) * 4,
                       Bg + (size_t)(kk + rB) * N + bn + cB);
        }
        asm volatile("cp.async.commit_group;\n" ::);
    };

    const int NC = k_len / GBK;
    load_tiles(0, k_begin);
    load_tiles(1, k_begin + GBK);

    for (int i = 0; i < NC; ++i) {
        if (i + 1 < NC) asm volatile("cp.async.wait_group 1;\n" ::);
        else            asm volatile("cp.async.wait_group 0;\n" ::);
        __syncthreads();
        if (i + 2 < NC)
            load_tiles((i + 2) % 3, k_begin + (i + 2) * GBK);

        const float* Ab = As + (i % 3) * AS_ELEMS;
        const float* Bb = Bs + (i % 3) * BS_ELEMS;

#pragma unroll
        for (int ks = 0; ks < 4; ++ks) {
            const int k0 = ks * 8;
            uint32_t af[4][4], bf[8][2];
#pragma unroll
            for (int mt = 0; mt < 4; ++mt) {
                const float* p0 = Ab + (x.rb + mt * 16 + x.g) * AS_STRIDE + k0 + x.c;
                const float* p1 = p0 + 8 * AS_STRIDE;
                af[mt][0] = __float_as_uint(p0[0]);
                af[mt][1] = __float_as_uint(p1[0]);
                af[mt][2] = __float_as_uint(p0[4]);
                af[mt][3] = __float_as_uint(p1[4]);
            }
#pragma unroll
            for (int nt = 0; nt < 8; ++nt) {
                const float* p = Bb + (k0 + x.c) * BS_STRIDE + x.nb + nt * 8 + x.g;
                bf[nt][0] = __float_as_uint(p[0]);
                bf[nt][1] = __float_as_uint(p[4 * BS_STRIDE]);
            }
#pragma unroll
            for (int mt = 0; mt < 4; ++mt)
#pragma unroll
                for (int nt = 0; nt < 8; ++nt)
                    mma_tf32(acc[mt][nt], af[mt], bf[nt]);
        }
    }
}

__device__ __forceinline__ void gemm_zero(float acc[4][8][4]) {
#pragma unroll
    for (int mt = 0; mt < 4; ++mt)
#pragma unroll
        for (int nt = 0; nt < 8; ++nt)
#pragma unroll
            for (int r = 0; r < 4; ++r) acc[mt][nt][r] = 0.0f;
}

// Generic GEMM with bias (+optional rna round) epilogue.
__global__ __launch_bounds__(128, 2)
void gemm_tf32(const float* __restrict__ A, const float* __restrict__ Bg,
               const float* __restrict__ bias, float* __restrict__ C,
               int M, int N, int K, int round_out)
{
    extern __shared__ float smem[];
    GemmCtx x; gemm_ctx_init(x);
    const int bm = blockIdx.y * GBM;
    const int bn = blockIdx.x * GBN;

    float acc[4][8][4];
    gemm_zero(acc);
    gemm_core(A, Bg, bm, bn, N, K, 0, K, smem, smem + 3 * AS_ELEMS, acc, x);

#pragma unroll
    for (int mt = 0; mt < 4; ++mt) {
        const int row0 = bm + x.rb + mt * 16 + x.g;
#pragma unroll
        for (int nt = 0; nt < 8; ++nt) {
            const int col = bn + x.nb + nt * 8 + 2 * x.c;
            const float2 bv = *(const float2*)&bias[col];
            float2 o0 = { acc[mt][nt][0] + bv.x, acc[mt][nt][1] + bv.y };
            float2 o1 = { acc[mt][nt][2] + bv.x, acc[mt][nt][3] + bv.y };
            if (round_out) {
                o0.x = rna_tf32(o0.x); o0.y = rna_tf32(o0.y);
                o1.x = rna_tf32(o1.x); o1.y = rna_tf32(o1.y);
            }
            *(float2*)&C[(size_t)row0 * N + col] = o0;
            *(float2*)&C[(size_t)(row0 + 8) * N + col] = o1;
        }
    }
}

// Fused projection kernel, 1-D grid of 1152 CTAs:
//  cta <  768: KV split-K partial (z=cta/96: split=z>>1, V=z&1), raw store
//  cta >= 768: Q projection (K=768), bias + rna epilogue
__global__ __launch_bounds__(128, 2)
void proj_fused(const float* __restrict__ Tgt, const float* __restrict__ Src,
                const float* __restrict__ Wq, const float* __restrict__ bq,
                float* __restrict__ Qout,
                const float* __restrict__ Wk, const float* __restrict__ Wv,
                float* __restrict__ Part)
{
    extern __shared__ float smem[];
    GemmCtx x; gemm_ctx_init(x);
    const int cta = blockIdx.x;

    float acc[4][8][4];
    gemm_zero(acc);

    if (cta < 768) {
        const int z = cta / 96;
        const int rem = cta % 96;
        const int bm = (rem / 6) * GBM;
        const int bn = (rem % 6) * GBN;
        const float* Bg = (z & 1) ? Wv : Wk;
        float* C = Part + (size_t)z * CS * CHE;

        gemm_core(Src, Bg, bm, bn, CHE, CDL, (z >> 1) * (CDL / 4), CDL / 4,
                  smem, smem + 3 * AS_ELEMS, acc, x);

#pragma unroll
        for (int mt = 0; mt < 4; ++mt) {
            const int row0 = bm + x.rb + mt * 16 + x.g;
#pragma unroll
            for (int nt = 0; nt < 8; ++nt) {
                const int col = bn + x.nb + nt * 8 + 2 * x.c;
                *(float2*)&C[(size_t)row0 * CHE + col] =
                    make_float2(acc[mt][nt][0], acc[mt][nt][1]);
                *(float2*)&C[(size_t)(row0 + 8) * CHE + col] =
                    make_float2(acc[mt][nt][2], acc[mt][nt][3]);
            }
        }
    } else {
        const int idx = cta - 768;
        const int bm = (idx / 6) * GBM;
        const int bn = (idx % 6) * GBN;

        gemm_core(Tgt, Wq, bm, bn, CHE, CDM, 0, CDM,
                  smem, smem + 3 * AS_ELEMS, acc, x);

#pragma unroll
        for (int mt = 0; mt < 4; ++mt) {
            const int row0 = bm + x.rb + mt * 16 + x.g;
#pragma unroll
            for (int nt = 0; nt < 8; ++nt) {
                const int col = bn + x.nb + nt * 8 + 2 * x.c;
                const float2 bv = *(const float2*)&bq[col];
                float2 o0 = { rna_tf32(acc[mt][nt][0] + bv.x),
                              rna_tf32(acc[mt][nt][1] + bv.y) };
                float2 o1 = { rna_tf32(acc[mt][nt][2] + bv.x),
                              rna_tf32(acc[mt][nt][3] + bv.y) };
                *(float2*)&Qout[(size_t)row0 * CHE + col] = o0;
                *(float2*)&Qout[(size_t)(row0 + 8) * CHE + col] = o1;
            }
        }
    }
}

// Reduce the 4 split-K partials for K and V, add bias, rna-round.
__global__ void reduce_kv(const float* __restrict__ part,
                          const float* __restrict__ bk, const float* __restrict__ bv,
                          float* __restrict__ Kout, float* __restrict__ Vout)
{
    const int i4 = blockIdx.x * blockDim.x + threadIdx.x;
    const int n4 = CS * CHE / 4;
    if (i4 >= n4) return;
    const size_t MN = (size_t)CS * CHE;
    const size_t off = (size_t)i4 * 4;
    const int col = (int)(off % CHE);

    float4 sk = make_float4(0.f, 0.f, 0.f, 0.f);
    float4 sv = make_float4(0.f, 0.f, 0.f, 0.f);
#pragma unroll
    for (int s = 0; s < 4; ++s) {
        float4 pk = *(const float4*)&part[(size_t)(2 * s) * MN + off];
        float4 pv = *(const float4*)&part[(size_t)(2 * s + 1) * MN + off];
        sk.x += pk.x; sk.y += pk.y; sk.z += pk.z; sk.w += pk.w;
        sv.x += pv.x; sv.y += pv.y; sv.z += pv.z; sv.w += pv.w;
    }
    float4 bkv = *(const float4*)&bk[col];
    float4 bvv = *(const float4*)&bv[col];
    float4 ok = { rna_tf32(sk.x + bkv.x), rna_tf32(sk.y + bkv.y),
                  rna_tf32(sk.z + bkv.z), rna_tf32(sk.w + bkv.w) };
    float4 ov = { rna_tf32(sv.x + bvv.x), rna_tf32(sv.y + bvv.y),
                  rna_tf32(sv.z + bvv.z), rna_tf32(sv.w + bvv.w) };
    *(float4*)&Kout[off] = ok;
    *(float4*)&Vout[off] = ov;
}

// ============================================================================
// Tensor-core flash attention (unchanged from R4/R8).
// ============================================================================
#define SQ  128
#define SC  64
#define QST 100
#define KST 100
#define VST 104
#define PST 68

#define ATTN_SMEM ((SQ * QST + 2 * SC * KST + 2 * SC * VST + SQ * PST) * 4)

__global__ __launch_bounds__(256, 1)
void attn_tc()
{
    extern __shared__ float sm[];
    float* Qs = sm;
    float* Ks = Qs + SQ * QST;
    float* Vs = Ks + 2 * SC * KST;
    float* Ps = Vs + 2 * SC * VST;

    const int tid  = threadIdx.x;
    const int w    = tid >> 5;
    const int lane = tid & 31;
    const int g = lane >> 2;
    const int c = lane & 3;
    const int bh = blockIdx.y;
    const int b = bh >> 3;
    const int h = bh & 7;
    const int q0 = blockIdx.x * SQ;
    const int r0 = w * 16 + g;

    const float qs = 0.1020620726159658f * 1.4426950408889634f;

    for (int i = tid; i < SQ * (CE / 4); i += 256) {
        const int r = i / (CE / 4);
        const int c4 = (i % (CE / 4)) * 4;
        float4 v = *(const float4*)&g_Q[((size_t)(b * CL + q0 + r)) * CHE + h * CE + c4];
        Qs[r * QST + c4 + 0] = rna_tf32(v.x * qs);
        Qs[r * QST + c4 + 1] = rna_tf32(v.y * qs);
        Qs[r * QST + c4 + 2] = rna_tf32(v.z * qs);
        Qs[r * QST + c4 + 3] = rna_tf32(v.w * qs);
    }
    __syncthreads();

    uint32_t qf[12][4];
#pragma unroll
    for (int ks = 0; ks < 12; ++ks) {
        const float* p = Qs + r0 * QST + ks * 8 + c;
        qf[ks][0] = __float_as_uint(p[0]);
        qf[ks][1] = __float_as_uint(p[8 * QST]);
        qf[ks][2] = __float_as_uint(p[4]);
        qf[ks][3] = __float_as_uint(p[8 * QST + 4]);
    }

    float oacc[12][4];
#pragma unroll
    for (int nt = 0; nt < 12; ++nt)
#pragma unroll
        for (int r = 0; r < 4; ++r) oacc[nt][r] = 0.0f;
    float m0 = -1e30f, m1 = -1e30f, l0 = 0.0f, l1 = 0.0f;

    const uint32_t sKs = (uint32_t)__cvta_generic_to_shared(Ks);
    const uint32_t sVs = (uint32_t)__cvta_generic_to_shared(Vs);

    auto load_kv = [&](int bufi, int s0) {
#pragma unroll
        for (int j = 0; j < 6; ++j) {
            const int idx = tid + j * 256;
            const int r = idx / (CE / 4);
            const int c4 = (idx % (CE / 4)) * 4;
            const size_t off = ((size_t)(s0 + r)) * CHE + h * CE + c4;
            cp_async16(sKs + (bufi * SC * KST + r * KST + c4) * 4, &g_K[off]);
            cp_async16(sVs + (bufi * SC * VST + r * VST + c4) * 4, &g_V[off]);
        }
        asm volatile("cp.async.commit_group;\n" ::);
    };

    load_kv(0, 0);
    int buf = 0;

    for (int it = 0; it < CS / SC; ++it) {
        if (it + 1 < CS / SC) {
            load_kv(buf ^ 1, (it + 1) * SC);
            asm volatile("cp.async.wait_group 1;\n" ::);
        } else {
            asm volatile("cp.async.wait_group 0;\n" ::);
        }
        __syncthreads();

        const float* Kb = Ks + buf * SC * KST;
        const float* Vb = Vs + buf * SC * VST;

        float sacc[8][4];
#pragma unroll
        for (int nt = 0; nt < 8; ++nt)
#pragma unroll
            for (int r = 0; r < 4; ++r) sacc[nt][r] = 0.0f;

#pragma unroll
        for (int ks = 0; ks < 12; ++ks) {
            uint32_t kf[8][2];
#pragma unroll
            for (int nt = 0; nt < 8; ++nt) {
                const float* p = Kb + (nt * 8 + g) * KST + ks * 8 + c;
                kf[nt][0] = __float_as_uint(p[0]);
                kf[nt][1] = __float_as_uint(p[4]);
            }
#pragma unroll
            for (int nt = 0; nt < 8; ++nt)
                mma_tf32(sacc[nt], qf[ks], kf[nt]);
        }

        float cm0 = -1e30f, cm1 = -1e30f;
#pragma unroll
        for (int nt = 0; nt < 8; ++nt) {
            cm0 = fmaxf(cm0, fmaxf(sacc[nt][0], sacc[nt][1]));
            cm1 = fmaxf(cm1, fmaxf(sacc[nt][2], sacc[nt][3]));
        }
        cm0 = fmaxf(cm0, __shfl_xor_sync(0xffffffffu, cm0, 1));
        cm0 = fmaxf(cm0, __shfl_xor_sync(0xffffffffu, cm0, 2));
        cm1 = fmaxf(cm1, __shfl_xor_sync(0xffffffffu, cm1, 1));
        cm1 = fmaxf(cm1, __shfl_xor_sync(0xffffffffu, cm1, 2));

        const float nm0 = fmaxf(m0, cm0);
        const float nm1 = fmaxf(m1, cm1);
        const float sc0 = ex2(m0 - nm0);
        const float sc1 = ex2(m1 - nm1);
        m0 = nm0; m1 = nm1;

        float rs0 = 0.0f, rs1 = 0.0f;
#pragma unroll
        for (int nt = 0; nt < 8; ++nt) {
            const float p00 = ex2(sacc[nt][0] - m0);
            const float p01 = ex2(sacc[nt][1] - m0);
            const float p10 = ex2(sacc[nt][2] - m1);
            const float p11 = ex2(sacc[nt][3] - m1);
            rs0 += p00 + p01;
            rs1 += p10 + p11;
            float* pr0 = Ps + r0 * PST + nt * 8 + 2 * c;
            pr0[0] = rna_tf32(p00);
            pr0[1] = rna_tf32(p01);
            float* pr1 = Ps + (r0 + 8) * PST + nt * 8 + 2 * c;
            pr1[0] = rna_tf32(p10);
            pr1[1] = rna_tf32(p11);
        }
        rs0 += __shfl_xor_sync(0xffffffffu, rs0, 1);
        rs0 += __shfl_xor_sync(0xffffffffu, rs0, 2);
        rs1 += __shfl_xor_sync(0xffffffffu, rs1, 1);
        rs1 += __shfl_xor_sync(0xffffffffu, rs1, 2);
        l0 = l0 * sc0 + rs0;
        l1 = l1 * sc1 + rs1;

#pragma unroll
        for (int nt = 0; nt < 12; ++nt) {
            oacc[nt][0] *= sc0; oacc[nt][1] *= sc0;
            oacc[nt][2] *= sc1; oacc[nt][3] *= sc1;
        }
        __syncwarp();

#pragma unroll
        for (int ks = 0; ks < 8; ++ks) {
            uint32_t pf[4];
            const float* pp = Ps + r0 * PST + ks * 8 + c;
            pf[0] = __float_as_uint(pp[0]);
            pf[1] = __float_as_uint(pp[8 * PST]);
            pf[2] = __float_as_uint(pp[4]);
            pf[3] = __float_as_uint(pp[8 * PST + 4]);
#pragma unroll
            for (int nt = 0; nt < 12; ++nt) {
                const float* vp = Vb + (ks * 8 + c) * VST + nt * 8 + g;
                uint32_t vf[2];
                vf[0] = __float_as_uint(vp[0]);
                vf[1] = __float_as_uint(vp[4 * VST]);
                mma_tf32(oacc[nt], pf, vf);
            }
        }
        __syncthreads();
        buf ^= 1;
    }

    const float inv0 = 1.0f / l0;
    const float inv1 = 1.0f / l1;
    const size_t row0 = ((size_t)(b * CL + q0 + r0)) * CHE + h * CE;
    const size_t row1 = ((size_t)(b * CL + q0 + r0 + 8)) * CHE + h * CE;
#pragma unroll
    for (int nt = 0; nt < 12; ++nt) {
        const int col = nt * 8 + 2 * c;
        float2 o0 = { rna_tf32(oacc[nt][0] * inv0), rna_tf32(oacc[nt][1] * inv0) };
        float2 o1 = { rna_tf32(oacc[nt][2] * inv1), rna_tf32(oacc[nt][3] * inv1) };
        *(float2*)&g_rep[row0 + col] = o0;
        *(float2*)&g_rep[row1 + col] = o1;
    }
}

// ============================================================================
// Launch
// ============================================================================
extern "C" void kernel_launch(void* const* d_in, const int* in_sizes, int n_in,
                              void* d_out, int out_size)
{
    const float* target = (const float*)d_in[0];
    const float* source = (const float*)d_in[1];
    const float* Wq = (const float*)d_in[2];
    const float* bq = (const float*)d_in[3];
    const float* Wk = (const float*)d_in[4];
    const float* bk = (const float*)d_in[5];
    const float* Wv = (const float*)d_in[6];
    const float* bv = (const float*)d_in[7];
    const float* Wo = (const float*)d_in[8];
    const float* bo = (const float*)d_in[9];
    float* out = (float*)d_out;

    float *Qp, *Kp, *Vp, *Rp, *Tp, *Sp, *Wqp, *Wkp, *Wvp, *Wop, *Pp;
    cudaGetSymbolAddress((void**)&Qp, g_Q);
    cudaGetSymbolAddress((void**)&Kp, g_K);
    cudaGetSymbolAddress((void**)&Vp, g_V);
    cudaGetSymbolAddress((void**)&Rp, g_rep);
    cudaGetSymbolAddress((void**)&Tp, g_tgt);
    cudaGetSymbolAddress((void**)&Sp, g_src);
    cudaGetSymbolAddress((void**)&Wqp, g_wq);
    cudaGetSymbolAddress((void**)&Wkp, g_wk);
    cudaGetSymbolAddress((void**)&Wvp, g_wv);
    cudaGetSymbolAddress((void**)&Wop, g_wo);
    cudaGetSymbolAddress((void**)&Pp, g_kvpart);

    cudaFuncSetAttribute(gemm_tf32, cudaFuncAttributeMaxDynamicSharedMemorySize,
                         GEMM_SMEM);
    cudaFuncSetAttribute(proj_fused, cudaFuncAttributeMaxDynamicSharedMemorySize,
                         GEMM_SMEM);
    cudaFuncSetAttribute(attn_tc, cudaFuncAttributeMaxDynamicSharedMemorySize,
                         ATTN_SMEM);

    // Pre-round GEMM inputs to tf32 (rna)
    auto rr = [&](const float* s, float* d, int n) {
        const int n4 = n / 4;
        round_tf32_kernel<<<(n4 + 255) / 256, 256>>>((const float4*)s, (float4*)d, n4);
    };
    rr(target, Tp, CB * CL * CDM);
    rr(source, Sp, CS * CDL);
    rr(Wq, Wqp, CDM * CHE);
    rr(Wk, Wkp, CDL * CHE);
    rr(Wv, Wvp, CDL * CHE);
    rr(Wo, Wop, CHE * CDL);

    // Fused Q projection + K/V split-K partials (1152 CTAs, 128 threads)
    proj_fused<<<1152, 128, GEMM_SMEM>>>(Tp, Sp, Wqp, bq, Qp, Wkp, Wvp, Pp);

    // Reduce K/V partials (+bias, rna)
    {
        const int n4 = CS * CHE / 4;
        reduce_kv<<<(n4 + 255) / 256, 256>>>(Pp, bk, bv, Kp, Vp);
    }

    // Attention -> rep (tensor-core, rounded epilogue)
    attn_tc<<<dim3(CL / SQ, CB * CH), dim3(256), ATTN_SMEM>>>();

    // out = rep @ Wo + bo   (8192 x 4096, K=768), full fp32 epilogue
    gemm_tf32<<<dim3(CDL / GBN, (CB * CL) / GBM), 128, GEMM_SMEM>>>(
        Rp, Wop, bo, out, CB * CL, CDL, CHE, 0);
}